// round 2
// baseline (speedup 1.0000x reference)
#include <cuda_runtime.h>
#include <math.h>
#include <stdint.h>

// Problem constants
constexpr int NB  = 32;     // batch
constexpr int NS  = 64;     // src len
constexpr int NT  = 48;     // tgt len
constexpr int NTm1= 47;     // decode steps
constexpr int NV  = 32000;  // vocab
constexpr int NE  = 512;    // embed
constexpr int NH  = 1024;   // hidden
constexpr int NH3 = 3072;   // 3*H
constexpr int NEH = NE+NH;  // 1536

// ---------------- scratch (device globals; no allocation allowed) -------------
__device__ float g_emb   [NB*NS*NE];        // encoder embeddings      (4 MB)
__device__ float g_gi0   [NB*NS*NH3];       // enc layer0 input gates  (25 MB)
__device__ float g_encout[NB*NS*NH];        // encoder outputs         (8 MB)
__device__ float g_proj  [NB*NS*NH];        // attn-projected enc out  (8 MB)
__device__ float g_h0    [NB*NH];
__device__ float g_h1    [NB*NH];
__device__ float g_gi    [NB*NH3];
__device__ float g_gh    [NB*NH3];
__device__ float g_x     [NB*NEH];          // decoder input [emb, ctx]
__device__ float g_d1ctx [NTm1*NB*2*NH];    // rows (t*B+b): [d1(1024), ctx(1024)]

// ---------------- generic C = A(MxK) * W(NxK)^T + bias GEMM ------------------
template<int BM,int BN,int BK,int TM,int TN,bool REMAP>
__global__ void gemm_tn(const float* __restrict__ A, const float* __restrict__ W,
                        const float* __restrict__ bias, float* __restrict__ C,
                        int M, int N, int K)
{
    constexpr int TX = BN/TN, TY = BM/TM, THREADS = TX*TY;
    __shared__ float As[BK][BM];
    __shared__ float Ws[BK][BN];
    const int bm = blockIdx.y * BM;
    const int bn = blockIdx.x * BN;
    const int tid = threadIdx.x;
    const int ty = tid / TX, tx = tid % TX;
    const int rm = ty * TM, rn = tx * TN;

    float acc[TM][TN];
#pragma unroll
    for (int i = 0; i < TM; i++)
#pragma unroll
        for (int j = 0; j < TN; j++) acc[i][j] = 0.f;

    for (int k0 = 0; k0 < K; k0 += BK) {
#pragma unroll
        for (int i = tid; i < BM*BK; i += THREADS) {
            int m = i / BK, k = i % BK;
            int gm = bm + m;
            As[k][m] = (gm < M) ? A[(size_t)gm * K + k0 + k] : 0.f;
        }
#pragma unroll
        for (int i = tid; i < BN*BK; i += THREADS) {
            int n = i / BK, k = i % BK;
            Ws[k][n] = W[(size_t)(bn + n) * K + k0 + k];
        }
        __syncthreads();
#pragma unroll
        for (int kk = 0; kk < BK; kk++) {
            float a[TM], w[TN];
#pragma unroll
            for (int i = 0; i < TM; i++) a[i] = As[kk][rm + i];
#pragma unroll
            for (int j = 0; j < TN; j++) w[j] = Ws[kk][rn + j];
#pragma unroll
            for (int i = 0; i < TM; i++)
#pragma unroll
                for (int j = 0; j < TN; j++)
                    acc[i][j] += a[i] * w[j];
        }
        __syncthreads();
    }

#pragma unroll
    for (int i = 0; i < TM; i++) {
        int gm = bm + rm + i;
        if (gm >= M) continue;
#pragma unroll
        for (int j = 0; j < TN; j++) {
            int gn = bn + rn + j;
            float v = acc[i][j] + (bias ? bias[gn] : 0.f);
            if (REMAP) {
                // row gm = t*NB + b  ->  out[b][t][gn]   (B, T-1, V)
                int tt = gm / NB, bb = gm % NB;
                C[(size_t)bb * ((size_t)NTm1 * NV) + (size_t)tt * NV + gn] = v;
            } else {
                C[(size_t)gm * N + gn] = v;
            }
        }
    }
}

// ---------------- elementwise GRU gate fusion --------------------------------
// gi includes bih (added by GEMM); gh includes bhh.
__global__ void gru_gate_kernel(const float* __restrict__ gi, long gi_bstride,
                                const float* __restrict__ gh,
                                float* __restrict__ h,
                                float* __restrict__ extra, long extra_bstride)
{
    int idx = blockIdx.x * blockDim.x + threadIdx.x;
    if (idx >= NB * NH) return;
    int b = idx >> 10;
    int j = idx & (NH - 1);
    const float* gib = gi + (size_t)b * gi_bstride;
    const float* ghb = gh + (size_t)b * NH3;
    float r = 1.f / (1.f + expf(-(gib[j]        + ghb[j])));
    float z = 1.f / (1.f + expf(-(gib[NH + j]   + ghb[NH + j])));
    float n = tanhf(gib[2*NH + j] + r * ghb[2*NH + j]);
    float hv = h[idx];
    float hn = (1.f - z) * n + z * hv;
    h[idx] = hn;
    if (extra) extra[(size_t)b * extra_bstride + j] = hn;
}

// ---------------- misc small kernels -----------------------------------------
__global__ void zero2_kernel(float* a, float* b, int n)
{
    int i = blockIdx.x * blockDim.x + threadIdx.x;
    if (i < n) { a[i] = 0.f; b[i] = 0.f; }
}

__global__ void embed_enc_kernel(const int* __restrict__ src_ids,
                                 const float* __restrict__ enc_emb,
                                 float* __restrict__ emb)
{
    int idx = blockIdx.x * blockDim.x + threadIdx.x;   // over B*S*E/4
    if (idx >= NB*NS*NE/4) return;
    int row = idx / (NE/4);
    int c4  = idx % (NE/4);
    const float4* src = (const float4*)(enc_emb + (size_t)src_ids[row] * NE);
    ((float4*)emb)[idx] = src[c4];
}

// One block per batch row: scores (masked) -> softmax -> context -> also gathers
// the decoder token embedding into x. ctx is written both to x[:, E:] and the
// second half of the d1ctx row for this step.
__global__ void attn_fused_kernel(const float* __restrict__ proj,
                                  const float* __restrict__ enc_out,
                                  const float* __restrict__ d1,
                                  const int*   __restrict__ src_ids,
                                  const int*   __restrict__ tgt_ids,
                                  const float* __restrict__ dec_emb,
                                  float* __restrict__ x,
                                  float* __restrict__ d1ctx_t,
                                  int t)
{
    int b   = blockIdx.x;
    int tid = threadIdx.x;            // 256 threads
    int warp = tid >> 5, lane = tid & 31;

    __shared__ float s_d1[NH];
    __shared__ float s_sc[NS];
    __shared__ float s_attn[NS];

    for (int i = tid; i < NH; i += 256) s_d1[i] = d1[(size_t)b * NH + i];
    __syncthreads();

    for (int s = warp; s < NS; s += 8) {
        const float* pr = proj + (size_t)(b * NS + s) * NH;
        float acc = 0.f;
        for (int k = lane; k < NH; k += 32) acc += pr[k] * s_d1[k];
#pragma unroll
        for (int off = 16; off; off >>= 1) acc += __shfl_xor_sync(0xffffffffu, acc, off);
        if (lane == 0)
            s_sc[s] = (src_ids[b * NS + s] != 0) ? acc : -1e9f;
    }
    __syncthreads();

    if (warp == 0) {
        float v0 = s_sc[lane], v1 = s_sc[lane + 32];
        float m = fmaxf(v0, v1);
#pragma unroll
        for (int off = 16; off; off >>= 1) m = fmaxf(m, __shfl_xor_sync(0xffffffffu, m, off));
        float e0 = expf(v0 - m), e1 = expf(v1 - m);
        float sum = e0 + e1;
#pragma unroll
        for (int off = 16; off; off >>= 1) sum += __shfl_xor_sync(0xffffffffu, sum, off);
        float inv = 1.f / sum;
        s_attn[lane]      = e0 * inv;
        s_attn[lane + 32] = e1 * inv;
    }
    __syncthreads();

    for (int j = tid; j < NH; j += 256) {
        float acc = 0.f;
#pragma unroll 8
        for (int s = 0; s < NS; s++)
            acc += s_attn[s] * enc_out[(size_t)(b * NS + s) * NH + j];
        x[(size_t)b * NEH + NE + j] = acc;
        d1ctx_t[(size_t)b * (2 * NH) + NH + j] = acc;
    }

    int tok = tgt_ids[b * NT + t];
    for (int i = tid; i < NE; i += 256)
        x[(size_t)b * NEH + i] = dec_emb[(size_t)tok * NE + i];
}

// ---------------- host orchestration -----------------------------------------
using GemmBig   = void(*)(const float*, const float*, const float*, float*, int, int, int);

extern "C" void kernel_launch(void* const* d_in, const int* in_sizes, int n_in,
                              void* d_out, int out_size)
{
    const int*   src_ids  = (const int*)  d_in[0];
    // d_in[1] = src_lens (all full; packing is a no-op)
    const int*   tgt_ids  = (const int*)  d_in[2];
    const float* enc_emb  = (const float*)d_in[3];
    const float* dec_emb  = (const float*)d_in[4];
    const float* enc_wih0 = (const float*)d_in[5];
    const float* enc_whh0 = (const float*)d_in[6];
    const float* enc_bih0 = (const float*)d_in[7];
    const float* enc_bhh0 = (const float*)d_in[8];
    const float* enc_wih1 = (const float*)d_in[9];
    const float* enc_whh1 = (const float*)d_in[10];
    const float* enc_bih1 = (const float*)d_in[11];
    const float* enc_bhh1 = (const float*)d_in[12];
    const float* dec_wih0 = (const float*)d_in[13];
    const float* dec_whh0 = (const float*)d_in[14];
    const float* dec_bih0 = (const float*)d_in[15];
    const float* dec_bhh0 = (const float*)d_in[16];
    const float* dec_wih1 = (const float*)d_in[17];
    const float* dec_whh1 = (const float*)d_in[18];
    const float* dec_bih1 = (const float*)d_in[19];
    const float* dec_bhh1 = (const float*)d_in[20];
    const float* attn_w   = (const float*)d_in[21];
    const float* out_w    = (const float*)d_in[22];
    const float* out_b    = (const float*)d_in[23];
    float* out = (float*)d_out;

    float *p_emb, *p_gi0, *p_encout, *p_proj, *p_h0, *p_h1, *p_gi, *p_gh, *p_x, *p_d1ctx;
    cudaGetSymbolAddress((void**)&p_emb,    g_emb);
    cudaGetSymbolAddress((void**)&p_gi0,    g_gi0);
    cudaGetSymbolAddress((void**)&p_encout, g_encout);
    cudaGetSymbolAddress((void**)&p_proj,   g_proj);
    cudaGetSymbolAddress((void**)&p_h0,     g_h0);
    cudaGetSymbolAddress((void**)&p_h1,     g_h1);
    cudaGetSymbolAddress((void**)&p_gi,     g_gi);
    cudaGetSymbolAddress((void**)&p_gh,     g_gh);
    cudaGetSymbolAddress((void**)&p_x,      g_x);
    cudaGetSymbolAddress((void**)&p_d1ctx,  g_d1ctx);

    const int GATE_BLOCKS = (NB * NH + 255) / 256;

    // ---- encoder ----
    zero2_kernel<<<(NB*NH + 255)/256, 256>>>(p_h0, p_h1, NB*NH);
    embed_enc_kernel<<<(NB*NS*NE/4 + 255)/256, 256>>>(src_ids, enc_emb, p_emb);

    // all-steps layer-0 input gates: (B*S, E) @ wih0^T -> (B*S, 3H)
    gemm_tn<64,64,16,4,4,false><<<dim3(NH3/64, (NB*NS)/64), 256>>>(
        p_emb, enc_wih0, enc_bih0, p_gi0, NB*NS, NH3, NE);

    for (int s = 0; s < NS; s++) {
        gemm_tn<32,64,32,2,4,false><<<dim3(NH3/64, 1), 256>>>(
            p_h0, enc_whh0, enc_bhh0, p_gh, NB, NH3, NH);
        gru_gate_kernel<<<GATE_BLOCKS, 256>>>(
            p_gi0 + (size_t)s * NH3, (long)NS * NH3, p_gh, p_h0, nullptr, 0);

        gemm_tn<32,64,32,2,4,false><<<dim3(NH3/64, 1), 256>>>(
            p_h0, enc_wih1, enc_bih1, p_gi, NB, NH3, NH);
        gemm_tn<32,64,32,2,4,false><<<dim3(NH3/64, 1), 256>>>(
            p_h1, enc_whh1, enc_bhh1, p_gh, NB, NH3, NH);
        gru_gate_kernel<<<GATE_BLOCKS, 256>>>(
            p_gi, NH3, p_gh, p_h1, p_encout + (size_t)s * NH, (long)NS * NH);
    }

    // attention projection: (B*S, H) @ attn_w^T -> (B*S, H)
    gemm_tn<64,64,16,4,4,false><<<dim3(NH/64, (NB*NS)/64), 256>>>(
        p_encout, attn_w, nullptr, p_proj, NB*NS, NH, NH);

    // ---- decoder (d0 := h0, d1 := h1 continue in place) ----
    for (int t = 0; t < NTm1; t++) {
        attn_fused_kernel<<<NB, 256>>>(
            p_proj, p_encout, p_h1, src_ids, tgt_ids, dec_emb,
            p_x, p_d1ctx + (size_t)t * NB * 2 * NH, t);

        gemm_tn<32,64,32,2,4,false><<<dim3(NH3/64, 1), 256>>>(
            p_x, dec_wih0, dec_bih0, p_gi, NB, NH3, NEH);
        gemm_tn<32,64,32,2,4,false><<<dim3(NH3/64, 1), 256>>>(
            p_h0, dec_whh0, dec_bhh0, p_gh, NB, NH3, NH);
        gru_gate_kernel<<<GATE_BLOCKS, 256>>>(
            p_gi, NH3, p_gh, p_h0, nullptr, 0);

        gemm_tn<32,64,32,2,4,false><<<dim3(NH3/64, 1), 256>>>(
            p_h0, dec_wih1, dec_bih1, p_gi, NB, NH3, NH);
        gemm_tn<32,64,32,2,4,false><<<dim3(NH3/64, 1), 256>>>(
            p_h1, dec_whh1, dec_bhh1, p_gh, NB, NH3, NH);
        gru_gate_kernel<<<GATE_BLOCKS, 256>>>(
            p_gi, NH3, p_gh, p_h1,
            p_d1ctx + (size_t)t * NB * 2 * NH, (long)2 * NH);
    }

    // ---- deferred output projection: (T-1*B, 2H) @ out_w^T + out_b ----------
    gemm_tn<64,64,16,4,4,true><<<dim3(NV/64, (NTm1*NB + 63)/64), 256>>>(
        p_d1ctx, out_w, out_b, out, NTm1*NB, NV, 2*NH);

    (void)in_sizes; (void)n_in; (void)out_size;
}

// round 3
// speedup vs baseline: 7.1157x; 7.1157x over previous
#include <cuda_runtime.h>
#include <cuda_bf16.h>
#include <mma.h>
#include <math.h>
#include <stdint.h>

using namespace nvcuda;

// Problem constants
constexpr int NB  = 32;     // batch
constexpr int NS  = 64;     // src len
constexpr int NT  = 48;     // tgt len
constexpr int NTm1= 47;     // decode steps
constexpr int NV  = 32000;  // vocab
constexpr int NE  = 512;    // embed
constexpr int NH  = 1024;   // hidden
constexpr int NH3 = 3072;   // 3*H

// ---------------- scratch (device globals; no allocation allowed) -------------
__device__ float g_emb   [NB*NS*NE];        // enc embeddings (rows b*NS+s)
__device__ float g_demb  [NTm1*NB*NE];      // dec embeddings (rows t*NB+b)
__device__ float g_gi0   [NB*NS*NH3];       // enc l0 input gates (rows b*NS+s)
__device__ float g_gi1   [NS*NB*NH3];       // enc l1 input gates (rows s*NB+b)
__device__ float g_giemb [NTm1*NB*NH3];     // dec l0 emb-part gates (rows t*NB+b)
__device__ float g_h0seq [NS*NB*NH];        // enc l0 hidden per step (s-major)
__device__ float g_encout[NS*NB*NH];        // enc l1 hidden per step (s-major)
__device__ float g_proj  [NS*NB*NH];        // attn-projected enc out (s-major)
__device__ float g_ctx   [NB*NH];
__device__ float g_d0a[NB*NH], g_d0b[NB*NH];
__device__ float g_d1a[NB*NH], g_d1b[NB*NH];
__device__ float g_zero  [NB*NH];
__device__ float g_d1ctx [NTm1*NB*2*NH];    // rows (b*NTm1+t): [d1 | ctx]

// packed recurrent weights: [jb(128)][k(1024)][c(24)]  c = gate*8 + jj
__device__ float g_p_ewhh0[128*NH*24];
__device__ float g_p_ewhh1[128*NH*24];
__device__ float g_p_dwih0c[128*NH*24];     // dec_wih0[:, 512:1536]
__device__ float g_p_dwhh0[128*NH*24];
__device__ float g_p_dwih1[128*NH*24];
__device__ float g_p_dwhh1[128*NH*24];

// bf16 hi/lo splits for output projection
__device__ __nv_bfloat16 g_Ahi[1536*2048];
__device__ __nv_bfloat16 g_Alo[1536*2048];
__device__ __nv_bfloat16 g_Whi[(size_t)NV*2048];
__device__ __nv_bfloat16 g_Wlo[(size_t)NV*2048];

// ---------------- generic C = A(MxK) @ W(NxK)^T + bias (fp32 SIMT) -----------
template<int BM,int BN,int BK,int TM,int TN>
__global__ __launch_bounds__(256) void gemm_tn(
    const float* __restrict__ A, int lda,
    const float* __restrict__ W, int ldw,
    const float* __restrict__ bias, float* __restrict__ C,
    int M, int N, int K)
{
    constexpr int TX = BN/TN, TY = BM/TM, THREADS = TX*TY;
    __shared__ float As[BK][BM];
    __shared__ float Ws[BK][BN];
    const int bm = blockIdx.y * BM;
    const int bn = blockIdx.x * BN;
    const int tid = threadIdx.x;
    const int ty = tid / TX, tx = tid % TX;
    const int rm = ty * TM, rn = tx * TN;

    float acc[TM][TN];
#pragma unroll
    for (int i = 0; i < TM; i++)
#pragma unroll
        for (int j = 0; j < TN; j++) acc[i][j] = 0.f;

    for (int k0 = 0; k0 < K; k0 += BK) {
#pragma unroll
        for (int i = tid; i < BM*BK; i += THREADS) {
            int m = i / BK, k = i % BK;
            int gm = bm + m;
            As[k][m] = (gm < M) ? A[(size_t)gm * lda + k0 + k] : 0.f;
        }
#pragma unroll
        for (int i = tid; i < BN*BK; i += THREADS) {
            int n = i / BK, k = i % BK;
            Ws[k][n] = W[(size_t)(bn + n) * ldw + k0 + k];
        }
        __syncthreads();
#pragma unroll
        for (int kk = 0; kk < BK; kk++) {
            float a[TM], w[TN];
#pragma unroll
            for (int i = 0; i < TM; i++) a[i] = As[kk][rm + i];
#pragma unroll
            for (int j = 0; j < TN; j++) w[j] = Ws[kk][rn + j];
#pragma unroll
            for (int i = 0; i < TM; i++)
#pragma unroll
                for (int j = 0; j < TN; j++)
                    acc[i][j] += a[i] * w[j];
        }
        __syncthreads();
    }

#pragma unroll
    for (int i = 0; i < TM; i++) {
        int gm = bm + rm + i;
        if (gm >= M) continue;
#pragma unroll
        for (int j = 0; j < TN; j++) {
            int gn = bn + rn + j;
            C[(size_t)gm * N + gn] = acc[i][j] + (bias ? bias[gn] : 0.f);
        }
    }
}

// ---------------- weight panel packing ----------------------------------------
// Wp[jb][k][c] = W[(g*NH + jb*8 + jj)*ldw + koff + k],  c = g*8+jj, K=1024
__global__ void pack_w(const float* __restrict__ W, float* __restrict__ Wp,
                       int ldw, int koff)
{
    int col = blockIdx.y;            // 0..3071 = jb*24 + c
    int jb = col / 24, c = col % 24;
    int g = c >> 3, jj = c & 7;
    int row = g * NH + jb * 8 + jj;
    for (int k = blockIdx.x * 256 + threadIdx.x; k < NH; k += gridDim.x * 256)
        Wp[((size_t)jb * NH + k) * 24 + c] = W[(size_t)row * ldw + koff + k];
}

// ---------------- fused GRU layer step ----------------------------------------
// Two GEMM "jobs" (128 threads each, tile 32m x 24c panels), then gate math.
// MERGE=true: both jobs are halves of the gh GEMM (k-split); gi comes from gi_pre.
// MERGE=false: job0 = gi (A1@W1), job1 = gh (A2@W2).
template<bool MERGE>
__global__ __launch_bounds__(256) void gru_fused(
    const float* __restrict__ A1, int lda1, const float* __restrict__ W1p, long wjb1,
    const float* __restrict__ A2, int lda2, const float* __restrict__ W2p, long wjb2,
    int NK,
    const float* __restrict__ gi_pre, long gi_stride,
    const float* __restrict__ bih, const float* __restrict__ bhh,
    const float* __restrict__ h_in, float* __restrict__ h_out,
    float* __restrict__ extra, long extra_stride)
{
    __shared__ float sA1[32][34];
    __shared__ float sW1[32][26];
    __shared__ float sA2[32][34];
    __shared__ float sW2[32][26];
    __shared__ float sG1[32][24];
    __shared__ float sG2[32][24];

    const int jb = blockIdx.x;       // 0..127
    const int tid = threadIdx.x;
    const int grp = tid >> 7;
    const int t2 = tid & 127;
    const int cg = t2 & 7;
    const int mg = t2 >> 3;          // 0..15
    const int m0 = mg * 2;
    const int c0 = cg * 3;

    float acc[2][3] = {{0.f,0.f,0.f},{0.f,0.f,0.f}};

    const float (*sA)[34] = grp ? sA2 : sA1;
    const float (*sW)[26] = grp ? sW2 : sW1;

    const float* Wblk1 = W1p + (size_t)jb * wjb1;
    const float* Wblk2 = W2p + (size_t)jb * wjb2;

    for (int it = 0; it < NK; it++) {
        const int k0 = it * 32;
#pragma unroll
        for (int e = tid; e < 1024; e += 256) {
            int m = e >> 5, kk = e & 31;
            sA1[kk][m] = A1[(size_t)m * lda1 + k0 + kk];
            sA2[kk][m] = A2[(size_t)m * lda2 + k0 + kk];
        }
#pragma unroll
        for (int e = tid; e < 768; e += 256) {
            int kk = e / 24, c = e % 24;
            sW1[kk][c] = Wblk1[(size_t)(k0 + kk) * 24 + c];
            sW2[kk][c] = Wblk2[(size_t)(k0 + kk) * 24 + c];
        }
        __syncthreads();
#pragma unroll
        for (int kk = 0; kk < 32; kk++) {
            float a0 = sA[kk][m0], a1 = sA[kk][m0 + 1];
            float w0 = sW[kk][c0], w1 = sW[kk][c0 + 1], w2 = sW[kk][c0 + 2];
            acc[0][0] += a0 * w0; acc[0][1] += a0 * w1; acc[0][2] += a0 * w2;
            acc[1][0] += a1 * w0; acc[1][1] += a1 * w1; acc[1][2] += a1 * w2;
        }
        __syncthreads();
    }

    float (*sO)[24] = grp ? sG2 : sG1;
    sO[m0  ][c0] = acc[0][0]; sO[m0  ][c0+1] = acc[0][1]; sO[m0  ][c0+2] = acc[0][2];
    sO[m0+1][c0] = acc[1][0]; sO[m0+1][c0+1] = acc[1][1]; sO[m0+1][c0+2] = acc[1][2];
    __syncthreads();

    // epilogue: 256 threads = 32 m x 8 jj
    const int m = tid >> 3;
    const int jj = tid & 7;
    const int j = jb * 8 + jj;

    float g1r = sG1[m][jj], g1z = sG1[m][8+jj], g1n = sG1[m][16+jj];
    float ghr = sG2[m][jj], ghz = sG2[m][8+jj], ghn = sG2[m][16+jj];
    float gir, giz, gin;
    if (MERGE) { ghr += g1r; ghz += g1z; ghn += g1n; gir = giz = gin = 0.f; }
    else       { gir = g1r;  giz = g1z;  gin = g1n; }
    if (gi_pre) {
        const float* gp = gi_pre + (size_t)m * gi_stride;
        gir += gp[j]; giz += gp[NH + j]; gin += gp[2*NH + j];
    }
    if (bih) { gir += bih[j]; giz += bih[NH + j]; gin += bih[2*NH + j]; }
    ghr += bhh[j]; ghz += bhh[NH + j]; ghn += bhh[2*NH + j];

    float r = 1.f / (1.f + expf(-(gir + ghr)));
    float z = 1.f / (1.f + expf(-(giz + ghz)));
    float n = tanhf(gin + r * ghn);
    float hv = h_in[(size_t)m * NH + j];
    float hn = (1.f - z) * n + z * hv;
    h_out[(size_t)m * NH + j] = hn;
    if (extra) extra[(size_t)m * extra_stride + j] = hn;
}

// ---------------- attention (per-step) ----------------------------------------
__global__ void attn_kernel(const float* __restrict__ proj,
                            const float* __restrict__ enc_out,
                            const float* __restrict__ d1,
                            const int*   __restrict__ src_ids,
                            float* __restrict__ ctx_out,
                            float* __restrict__ ctx2, long ctx2_stride)
{
    int b   = blockIdx.x;
    int tid = threadIdx.x;            // 256 threads
    int warp = tid >> 5, lane = tid & 31;

    __shared__ float s_d1[NH];
    __shared__ float s_sc[NS];
    __shared__ float s_attn[NS];

    for (int i = tid; i < NH; i += 256) s_d1[i] = d1[(size_t)b * NH + i];
    __syncthreads();

    for (int s = warp; s < NS; s += 8) {
        const float* pr = proj + (size_t)(s * NB + b) * NH;
        float acc = 0.f;
        for (int k = lane; k < NH; k += 32) acc += pr[k] * s_d1[k];
#pragma unroll
        for (int off = 16; off; off >>= 1) acc += __shfl_xor_sync(0xffffffffu, acc, off);
        if (lane == 0)
            s_sc[s] = (src_ids[b * NS + s] != 0) ? acc : -1e9f;
    }
    __syncthreads();

    if (warp == 0) {
        float v0 = s_sc[lane], v1 = s_sc[lane + 32];
        float m = fmaxf(v0, v1);
#pragma unroll
        for (int off = 16; off; off >>= 1) m = fmaxf(m, __shfl_xor_sync(0xffffffffu, m, off));
        float e0 = expf(v0 - m), e1 = expf(v1 - m);
        float sum = e0 + e1;
#pragma unroll
        for (int off = 16; off; off >>= 1) sum += __shfl_xor_sync(0xffffffffu, sum, off);
        float inv = 1.f / sum;
        s_attn[lane]      = e0 * inv;
        s_attn[lane + 32] = e1 * inv;
    }
    __syncthreads();

    for (int jj = tid; jj < NH; jj += 256) {
        float acc = 0.f;
#pragma unroll 8
        for (int s = 0; s < NS; s++)
            acc += s_attn[s] * enc_out[(size_t)(s * NB + b) * NH + jj];
        ctx_out[(size_t)b * NH + jj] = acc;
        ctx2[(size_t)b * ctx2_stride + jj] = acc;
    }
}

// ---------------- small helpers -----------------------------------------------
__global__ void zero_kernel(float* a, int n)
{
    int i = blockIdx.x * blockDim.x + threadIdx.x;
    if (i < n) a[i] = 0.f;
}

__global__ void embed_enc_kernel(const int* __restrict__ src_ids,
                                 const float* __restrict__ enc_emb,
                                 float* __restrict__ emb)
{
    int idx = blockIdx.x * blockDim.x + threadIdx.x;   // over B*S*E/4
    if (idx >= NB*NS*NE/4) return;
    int row = idx / (NE/4);
    int c4  = idx % (NE/4);
    const float4* src = (const float4*)(enc_emb + (size_t)src_ids[row] * NE);
    ((float4*)emb)[idx] = src[c4];
}

__global__ void embed_dec_kernel(const int* __restrict__ tgt_ids,
                                 const float* __restrict__ dec_emb,
                                 float* __restrict__ demb)
{
    int idx = blockIdx.x * blockDim.x + threadIdx.x;   // over (T-1)*B*E/4
    if (idx >= NTm1*NB*NE/4) return;
    int row = idx / (NE/4);                             // t*NB + b
    int c4  = idx % (NE/4);
    int t = row / NB, b = row % NB;
    int tok = tgt_ids[b * NT + t];
    const float4* src = (const float4*)(dec_emb + (size_t)tok * NE);
    ((float4*)demb)[idx] = src[c4];
}

__global__ void convA_kernel(const float* __restrict__ A,
                             __nv_bfloat16* __restrict__ hi,
                             __nv_bfloat16* __restrict__ lo)
{
    int idx = blockIdx.x * blockDim.x + threadIdx.x;
    if (idx >= 1536 * 2048) return;
    int m = idx >> 11;
    float v = (m < NTm1 * NB) ? A[idx] : 0.f;
    __nv_bfloat16 h = __float2bfloat16(v);
    hi[idx] = h;
    lo[idx] = __float2bfloat16(v - __bfloat162float(h));
}

__global__ void convW_kernel(const float* __restrict__ W,
                             __nv_bfloat16* __restrict__ hi,
                             __nv_bfloat16* __restrict__ lo)
{
    size_t total = (size_t)NV * 2048;
    for (size_t idx = (size_t)blockIdx.x * blockDim.x + threadIdx.x;
         idx < total; idx += (size_t)gridDim.x * blockDim.x) {
        float v = W[idx];
        __nv_bfloat16 h = __float2bfloat16(v);
        hi[idx] = h;
        lo[idx] = __float2bfloat16(v - __bfloat162float(h));
    }
}

__global__ void bias_kernel(float* __restrict__ out, const float* __restrict__ bias)
{
    int idx = blockIdx.x * blockDim.x + threadIdx.x;   // over 1504*8000 float4
    if (idx >= NTm1 * NB * (NV/4)) return;
    int n4 = idx % (NV/4);
    float4 v = ((float4*)out)[idx];
    float4 bv = ((const float4*)bias)[n4];
    v.x += bv.x; v.y += bv.y; v.z += bv.z; v.w += bv.w;
    ((float4*)out)[idx] = v;
}

// ---------------- bf16 hi/lo wmma output projection ---------------------------
// C(1504x32000) = (Ahi+Alo)(Whi+Wlo)^T ~= AhiWhi + AhiWlo + AloWhi, fp32 accum
constexpr int OBM = 128, OBN = 128, OBK = 32, OLD = OBK + 8;

__global__ __launch_bounds__(256) void out_gemm(
    const __nv_bfloat16* __restrict__ Ahi, const __nv_bfloat16* __restrict__ Alo,
    const __nv_bfloat16* __restrict__ Bhi, const __nv_bfloat16* __restrict__ Blo,
    float* __restrict__ C)
{
    __shared__ __nv_bfloat16 sAh[OBM][OLD];
    __shared__ __nv_bfloat16 sAl[OBM][OLD];
    __shared__ __nv_bfloat16 sBh[OBN][OLD];
    __shared__ __nv_bfloat16 sBl[OBN][OLD];

    const int bm = blockIdx.x * OBM;    // 12 m-blocks (x-major for B reuse in L2)
    const int bn = blockIdx.y * OBN;    // 250 n-blocks
    const int tid = threadIdx.x;
    const int warp = tid >> 5;
    const int wm = warp >> 2, wn = warp & 3;   // 2 x 4 warps; warp tile 64 x 32

    wmma::fragment<wmma::accumulator,16,16,16,float> c[4][2];
#pragma unroll
    for (int i = 0; i < 4; i++)
#pragma unroll
        for (int j = 0; j < 2; j++) wmma::fill_fragment(c[i][j], 0.f);

    for (int k0 = 0; k0 < 2048; k0 += OBK) {
#pragma unroll
        for (int e = tid; e < OBM * 4; e += 256) {
            int r = e >> 2, q = e & 3;
            *(float4*)&sAh[r][q*8] = *(const float4*)&Ahi[(size_t)(bm + r) * 2048 + k0 + q*8];
            *(float4*)&sAl[r][q*8] = *(const float4*)&Alo[(size_t)(bm + r) * 2048 + k0 + q*8];
            *(float4*)&sBh[r][q*8] = *(const float4*)&Bhi[(size_t)(bn + r) * 2048 + k0 + q*8];
            *(float4*)&sBl[r][q*8] = *(const float4*)&Blo[(size_t)(bn + r) * 2048 + k0 + q*8];
        }
        __syncthreads();
#pragma unroll
        for (int ks = 0; ks < 2; ks++) {
            wmma::fragment<wmma::matrix_a,16,16,16,__nv_bfloat16,wmma::row_major> ah[4], al[4];
            wmma::fragment<wmma::matrix_b,16,16,16,__nv_bfloat16,wmma::col_major> bh[2], bl[2];
#pragma unroll
            for (int i = 0; i < 4; i++) {
                wmma::load_matrix_sync(ah[i], &sAh[wm*64 + i*16][ks*16], OLD);
                wmma::load_matrix_sync(al[i], &sAl[wm*64 + i*16][ks*16], OLD);
            }
#pragma unroll
            for (int j = 0; j < 2; j++) {
                wmma::load_matrix_sync(bh[j], &sBh[wn*32 + j*16][ks*16], OLD);
                wmma::load_matrix_sync(bl[j], &sBl[wn*32 + j*16][ks*16], OLD);
            }
#pragma unroll
            for (int i = 0; i < 4; i++)
#pragma unroll
                for (int j = 0; j < 2; j++) {
                    wmma::mma_sync(c[i][j], ah[i], bh[j], c[i][j]);
                    wmma::mma_sync(c[i][j], ah[i], bl[j], c[i][j]);
                    wmma::mma_sync(c[i][j], al[i], bh[j], c[i][j]);
                }
        }
        __syncthreads();
    }

#pragma unroll
    for (int i = 0; i < 4; i++) {
        int gm = bm + wm*64 + i*16;
        if (gm >= NTm1 * NB) continue;
#pragma unroll
        for (int j = 0; j < 2; j++)
            wmma::store_matrix_sync(&C[(size_t)gm * NV + bn + wn*32 + j*16],
                                    c[i][j], NV, wmma::mem_row_major);
    }
}

// ---------------- host orchestration -----------------------------------------
extern "C" void kernel_launch(void* const* d_in, const int* in_sizes, int n_in,
                              void* d_out, int out_size)
{
    const int*   src_ids  = (const int*)  d_in[0];
    const int*   tgt_ids  = (const int*)  d_in[2];
    const float* enc_emb  = (const float*)d_in[3];
    const float* dec_emb  = (const float*)d_in[4];
    const float* enc_wih0 = (const float*)d_in[5];
    const float* enc_whh0 = (const float*)d_in[6];
    const float* enc_bih0 = (const float*)d_in[7];
    const float* enc_bhh0 = (const float*)d_in[8];
    const float* enc_wih1 = (const float*)d_in[9];
    const float* enc_whh1 = (const float*)d_in[10];
    const float* enc_bih1 = (const float*)d_in[11];
    const float* enc_bhh1 = (const float*)d_in[12];
    const float* dec_wih0 = (const float*)d_in[13];
    const float* dec_whh0 = (const float*)d_in[14];
    const float* dec_bih0 = (const float*)d_in[15];
    const float* dec_bhh0 = (const float*)d_in[16];
    const float* dec_wih1 = (const float*)d_in[17];
    const float* dec_whh1 = (const float*)d_in[18];
    const float* dec_bih1 = (const float*)d_in[19];
    const float* dec_bhh1 = (const float*)d_in[20];
    const float* attn_w   = (const float*)d_in[21];
    const float* out_w    = (const float*)d_in[22];
    const float* out_b    = (const float*)d_in[23];
    float* out = (float*)d_out;

    float *p_emb,*p_demb,*p_gi0,*p_gi1,*p_giemb,*p_h0seq,*p_encout,*p_proj,*p_ctx;
    float *p_d0a,*p_d0b,*p_d1a,*p_d1b,*p_zero,*p_d1ctx;
    float *pw_ewhh0,*pw_ewhh1,*pw_dwih0c,*pw_dwhh0,*pw_dwih1,*pw_dwhh1;
    __nv_bfloat16 *p_Ahi,*p_Alo,*p_Whi,*p_Wlo;
    cudaGetSymbolAddress((void**)&p_emb,    g_emb);
    cudaGetSymbolAddress((void**)&p_demb,   g_demb);
    cudaGetSymbolAddress((void**)&p_gi0,    g_gi0);
    cudaGetSymbolAddress((void**)&p_gi1,    g_gi1);
    cudaGetSymbolAddress((void**)&p_giemb,  g_giemb);
    cudaGetSymbolAddress((void**)&p_h0seq,  g_h0seq);
    cudaGetSymbolAddress((void**)&p_encout, g_encout);
    cudaGetSymbolAddress((void**)&p_proj,   g_proj);
    cudaGetSymbolAddress((void**)&p_ctx,    g_ctx);
    cudaGetSymbolAddress((void**)&p_d0a,    g_d0a);
    cudaGetSymbolAddress((void**)&p_d0b,    g_d0b);
    cudaGetSymbolAddress((void**)&p_d1a,    g_d1a);
    cudaGetSymbolAddress((void**)&p_d1b,    g_d1b);
    cudaGetSymbolAddress((void**)&p_zero,   g_zero);
    cudaGetSymbolAddress((void**)&p_d1ctx,  g_d1ctx);
    cudaGetSymbolAddress((void**)&pw_ewhh0, g_p_ewhh0);
    cudaGetSymbolAddress((void**)&pw_ewhh1, g_p_ewhh1);
    cudaGetSymbolAddress((void**)&pw_dwih0c,g_p_dwih0c);
    cudaGetSymbolAddress((void**)&pw_dwhh0, g_p_dwhh0);
    cudaGetSymbolAddress((void**)&pw_dwih1, g_p_dwih1);
    cudaGetSymbolAddress((void**)&pw_dwhh1, g_p_dwhh1);
    cudaGetSymbolAddress((void**)&p_Ahi,    g_Ahi);
    cudaGetSymbolAddress((void**)&p_Alo,    g_Alo);
    cudaGetSymbolAddress((void**)&p_Whi,    g_Whi);
    cudaGetSymbolAddress((void**)&p_Wlo,    g_Wlo);

    const long WJB = (long)NH * 24;

    // ---- one-time-per-replay prep -------------------------------------------
    zero_kernel<<<(NB*NH + 255)/256, 256>>>(p_zero, NB*NH);
    pack_w<<<dim3(4, NH3), 256>>>(enc_whh0, pw_ewhh0, NH, 0);
    pack_w<<<dim3(4, NH3), 256>>>(enc_whh1, pw_ewhh1, NH, 0);
    pack_w<<<dim3(4, NH3), 256>>>(dec_wih0, pw_dwih0c, NE + NH, NE);
    pack_w<<<dim3(4, NH3), 256>>>(dec_whh0, pw_dwhh0, NH, 0);
    pack_w<<<dim3(4, NH3), 256>>>(dec_wih1, pw_dwih1, NH, 0);
    pack_w<<<dim3(4, NH3), 256>>>(dec_whh1, pw_dwhh1, NH, 0);
    convW_kernel<<<65536, 256>>>(out_w, p_Whi, p_Wlo);

    embed_enc_kernel<<<(NB*NS*NE/4 + 255)/256, 256>>>(src_ids, enc_emb, p_emb);
    embed_dec_kernel<<<(NTm1*NB*NE/4 + 255)/256, 256>>>(tgt_ids, dec_emb, p_demb);

    // batched input-gate GEMMs
    gemm_tn<64,64,16,4,4><<<dim3(NH3/64, (NB*NS)/64), 256>>>(
        p_emb, NE, enc_wih0, NE, enc_bih0, p_gi0, NB*NS, NH3, NE);
    gemm_tn<64,64,16,4,4><<<dim3(NH3/64, (NTm1*NB + 63)/64), 256>>>(
        p_demb, NE, dec_wih0, NE + NH, dec_bih0, p_giemb, NTm1*NB, NH3, NE);

    // ---- encoder layer 0 -----------------------------------------------------
    for (int s = 0; s < NS; s++) {
        const float* hp = s ? (p_h0seq + (size_t)(s-1)*NB*NH) : p_zero;
        gru_fused<true><<<128, 256>>>(
            hp + 512, NH, pw_ewhh0 + 512*24, WJB,
            hp,       NH, pw_ewhh0,          WJB,
            16,
            p_gi0 + (size_t)s * NH3, (long)NS * NH3,
            nullptr, enc_bhh0,
            hp, p_h0seq + (size_t)s*NB*NH, nullptr, 0);
    }

    // batched encoder layer-1 input gates
    gemm_tn<64,64,16,4,4><<<dim3(NH3/64, (NS*NB)/64), 256>>>(
        p_h0seq, NH, enc_wih1, NH, enc_bih1, p_gi1, NS*NB, NH3, NH);

    // ---- encoder layer 1 -----------------------------------------------------
    for (int s = 0; s < NS; s++) {
        const float* hp = s ? (p_encout + (size_t)(s-1)*NB*NH) : p_zero;
        gru_fused<true><<<128, 256>>>(
            hp + 512, NH, pw_ewhh1 + 512*24, WJB,
            hp,       NH, pw_ewhh1,          WJB,
            16,
            p_gi1 + (size_t)s * NB * NH3, (long)NH3,
            nullptr, enc_bhh1,
            hp, p_encout + (size_t)s*NB*NH, nullptr, 0);
    }

    // attention projection: (S*B, H) @ attn_w^T
    gemm_tn<64,64,16,4,4><<<dim3(NH/64, (NS*NB)/64), 256>>>(
        p_encout, NH, attn_w, NH, nullptr, p_proj, NS*NB, NH, NH);

    // ---- decoder -------------------------------------------------------------
    const float* d0_prev = p_h0seq  + (size_t)(NS-1)*NB*NH;
    const float* d1_prev = p_encout + (size_t)(NS-1)*NB*NH;
    for (int t = 0; t < NTm1; t++) {
        attn_kernel<<<NB, 256>>>(
            p_proj, p_encout, d1_prev, src_ids,
            p_ctx, p_d1ctx + (size_t)t * 2 * NH + NH, (long)NTm1 * 2 * NH);

        float* d0_new = (t & 1) ? p_d0b : p_d0a;
        gru_fused<false><<<128, 256>>>(
            p_ctx, NH, pw_dwih0c, WJB,
            d0_prev, NH, pw_dwhh0, WJB,
            32,
            p_giemb + (size_t)t * NB * NH3, (long)NH3,
            nullptr, dec_bhh0,
            d0_prev, d0_new, nullptr, 0);

        float* d1_new = (t & 1) ? p_d1b : p_d1a;
        gru_fused<false><<<128, 256>>>(
            d0_new, NH, pw_dwih1, WJB,
            d1_prev, NH, pw_dwhh1, WJB,
            32,
            nullptr, 0,
            dec_bih1, dec_bhh1,
            d1_prev, d1_new,
            p_d1ctx + (size_t)t * 2 * NH, (long)NTm1 * 2 * NH);

        d0_prev = d0_new;
        d1_prev = d1_new;
    }

    // ---- output projection on tensor cores ----------------------------------
    convA_kernel<<<(1536*2048 + 255)/256, 256>>>(p_d1ctx, p_Ahi, p_Alo);
    out_gemm<<<dim3(12, NV/OBN), 256>>>(p_Ahi, p_Alo, p_Whi, p_Wlo, out);
    bias_kernel<<<(NTm1*NB*(NV/4) + 255)/256, 256>>>(out, out_b);

    (void)in_sizes; (void)n_in; (void)out_size;
}

// round 4
// speedup vs baseline: 8.2727x; 1.1626x over previous
#include <cuda_runtime.h>
#include <cuda_bf16.h>
#include <mma.h>
#include <math.h>
#include <stdint.h>

using namespace nvcuda;
typedef __nv_bfloat16 bf16;

// Problem constants
constexpr int NB  = 32;     // batch
constexpr int NS  = 64;     // src len
constexpr int NT  = 48;     // tgt len
constexpr int NTm1= 47;     // decode steps
constexpr int NV  = 32000;  // vocab
constexpr int NE  = 512;    // embed
constexpr int NH  = 1024;   // hidden
constexpr int NH3 = 3072;   // 3*H

// ---------------- scratch (device globals; no allocation allowed) -------------
__device__ float g_gi0   [NB*NS*NH3];       // enc l0 input gates (rows b*NS+s)
__device__ float g_gi1   [NS*NB*NH3];       // enc l1 input gates (rows s*NB+b)
__device__ float g_giemb [NTm1*NB*NH3];     // dec l0 emb-part gates (rows t*NB+b)
__device__ float g_h0seq [NS*NB*NH];        // enc l0 hidden per step (s-major)
__device__ float g_encout[NS*NB*NH];        // enc l1 hidden per step (s-major)
__device__ float g_proj  [NS*NB*NH];        // attn-projected enc out (s-major)
__device__ float g_ctx   [NB*NH];
__device__ float g_d0a[NB*NH], g_d0b[NB*NH];
__device__ float g_d1a[NB*NH], g_d1b[NB*NH];
__device__ float g_zero  [NB*NH];
__device__ float g_d1ctx [NTm1*NB*2*NH];    // rows (b*NTm1+t): [d1 | ctx]

// packed recurrent weights: [jb(128)][k(1024)][c(24)]  c = gate*8 + jj
__device__ float g_p_ewhh0[128*NH*24];
__device__ float g_p_ewhh1[128*NH*24];
__device__ float g_p_dwih0c[128*NH*24];     // dec_wih0[:, 512:1536]
__device__ float g_p_dwhh0[128*NH*24];
__device__ float g_p_dwih1[128*NH*24];
__device__ float g_p_dwhh1[128*NH*24];

// bf16 hi/lo splits
__device__ bf16 g_Ahi[1536*2048],  g_Alo[1536*2048];       // d1ctx
__device__ bf16 g_Whi[(size_t)NV*2048], g_Wlo[(size_t)NV*2048];   // out_w
__device__ bf16 g_cembh[2048*512],  g_cembl[2048*512];     // enc embeddings
__device__ bf16 g_cdembh[1536*512], g_cdembl[1536*512];    // dec embeddings (pad)
__device__ bf16 g_ch0h[2048*1024],  g_ch0l[2048*1024];     // h0seq
__device__ bf16 g_ceoh[2048*1024],  g_ceol[2048*1024];     // encout
__device__ bf16 g_wih0h[3072*512],  g_wih0l[3072*512];     // enc_wih0
__device__ bf16 g_dwih0eh[3072*512],g_dwih0el[3072*512];   // dec_wih0[:, :512]
__device__ bf16 g_wih1h[3072*1024], g_wih1l[3072*1024];    // enc_wih1
__device__ bf16 g_attnwh[1024*1024],g_attnwl[1024*1024];   // attn_w

// ============ pipelined hi/lo bf16 tensor-core GEMM ===========================
// C(M x N) = (Ahi+Alo)(Bhi+Blo)^T ~= AhiBhi + AhiBlo + AloBhi  (fp32 accum)
// A: Mpad x K row-major (Mpad mult of 128), B: N x K row-major, K mult of 32.
constexpr int GLD  = 40;            // smem leading dim (elements)
constexpr int SBUF = 128 * GLD;     // one 128x32 buffer (padded)

__device__ __forceinline__ void cp16(bf16* s, const bf16* g)
{
    unsigned saddr = (unsigned)__cvta_generic_to_shared(s);
    asm volatile("cp.async.cg.shared.global [%0], [%1], 16;\n" :: "r"(saddr), "l"(g));
}

__device__ __forceinline__ void gemm_hl_load(
    int tid, int st, int k0, int bm, int bn, int K,
    const bf16* __restrict__ Ahi, const bf16* __restrict__ Alo,
    const bf16* __restrict__ Bhi, const bf16* __restrict__ Blo,
    bf16* sm)
{
#pragma unroll
    for (int i = 0; i < 8; i++) {
        int e = tid + i * 256;
        int buf = e >> 9;                 // 0..3 (constant per unrolled i)
        int r   = (e >> 2) & 127;
        int q   = e & 3;
        const bf16* gsrc; int grow;
        if      (buf == 0) { gsrc = Ahi; grow = bm + r; }
        else if (buf == 1) { gsrc = Alo; grow = bm + r; }
        else if (buf == 2) { gsrc = Bhi; grow = bn + r; }
        else               { gsrc = Blo; grow = bn + r; }
        bf16* s = sm + (size_t)buf * 2 * SBUF + (size_t)st * SBUF + r * GLD + q * 8;
        cp16(s, gsrc + (size_t)grow * K + k0 + q * 8);
    }
}

__global__ __launch_bounds__(256) void gemm_hl(
    const bf16* __restrict__ Ahi, const bf16* __restrict__ Alo,
    const bf16* __restrict__ Bhi, const bf16* __restrict__ Blo,
    float* __restrict__ C, int N, int K, int Mstore)
{
    extern __shared__ bf16 sm[];
    const int bm = blockIdx.x * 128;
    const int bn = blockIdx.y * 128;
    const int tid = threadIdx.x;
    const int warp = tid >> 5;
    const int wm = warp >> 2, wn = warp & 3;   // 2 x 4 warps; warp tile 64 x 32

    wmma::fragment<wmma::accumulator,16,16,16,float> c[4][2];
#pragma unroll
    for (int i = 0; i < 4; i++)
#pragma unroll
        for (int j = 0; j < 2; j++) wmma::fill_fragment(c[i][j], 0.f);

    const int NTk = K >> 5;

    gemm_hl_load(tid, 0, 0, bm, bn, K, Ahi, Alo, Bhi, Blo, sm);
    asm volatile("cp.async.commit_group;\n");

    for (int it = 0; it < NTk; it++) {
        if (it + 1 < NTk) {
            gemm_hl_load(tid, (it + 1) & 1, (it + 1) << 5, bm, bn, K, Ahi, Alo, Bhi, Blo, sm);
            asm volatile("cp.async.commit_group;\n");
            asm volatile("cp.async.wait_group 1;\n");
        } else {
            asm volatile("cp.async.wait_group 0;\n");
        }
        __syncthreads();

        const int cur = it & 1;
        const bf16* pAh = sm + 0 * 2 * SBUF + cur * SBUF;
        const bf16* pAl = sm + 1 * 2 * SBUF + cur * SBUF;
        const bf16* pBh = sm + 2 * 2 * SBUF + cur * SBUF;
        const bf16* pBl = sm + 3 * 2 * SBUF + cur * SBUF;

#pragma unroll
        for (int ks = 0; ks < 2; ks++) {
            wmma::fragment<wmma::matrix_a,16,16,16,bf16,wmma::row_major> ah[4], al[4];
            wmma::fragment<wmma::matrix_b,16,16,16,bf16,wmma::col_major> bh[2], bl[2];
#pragma unroll
            for (int i = 0; i < 4; i++) {
                wmma::load_matrix_sync(ah[i], pAh + (wm*64 + i*16)*GLD + ks*16, GLD);
                wmma::load_matrix_sync(al[i], pAl + (wm*64 + i*16)*GLD + ks*16, GLD);
            }
#pragma unroll
            for (int j = 0; j < 2; j++) {
                wmma::load_matrix_sync(bh[j], pBh + (wn*32 + j*16)*GLD + ks*16, GLD);
                wmma::load_matrix_sync(bl[j], pBl + (wn*32 + j*16)*GLD + ks*16, GLD);
            }
#pragma unroll
            for (int i = 0; i < 4; i++)
#pragma unroll
                for (int j = 0; j < 2; j++) {
                    wmma::mma_sync(c[i][j], ah[i], bh[j], c[i][j]);
                    wmma::mma_sync(c[i][j], ah[i], bl[j], c[i][j]);
                    wmma::mma_sync(c[i][j], al[i], bh[j], c[i][j]);
                }
        }
        __syncthreads();
    }

#pragma unroll
    for (int i = 0; i < 4; i++) {
        int gm = bm + wm*64 + i*16;
        if (gm >= Mstore) continue;
#pragma unroll
        for (int j = 0; j < 2; j++)
            wmma::store_matrix_sync(&C[(size_t)gm * N + bn + wn*32 + j*16],
                                    c[i][j], N, wmma::mem_row_major);
    }
}

// ---------------- fp32 -> bf16 hi/lo conversion (one block per row) ----------
__global__ void conv_hl(const float* __restrict__ src, int lda,
                        bf16* __restrict__ hi, bf16* __restrict__ lo,
                        int Mreal, int K)
{
    int m = blockIdx.x;
    const float* s = src + (size_t)m * lda;
    bf16* h = hi + (size_t)m * K;
    bf16* l = lo + (size_t)m * K;
    bool valid = m < Mreal;
    for (int k = threadIdx.x; k < K; k += blockDim.x) {
        float v = valid ? s[k] : 0.f;
        bf16 hv = __float2bfloat16(v);
        h[k] = hv;
        l[k] = __float2bfloat16(v - __bfloat162float(hv));
    }
}

// embedding gather fused with hi/lo conversion
__global__ void embed_enc_hl(const int* __restrict__ src_ids,
                             const float* __restrict__ enc_emb,
                             bf16* __restrict__ hi, bf16* __restrict__ lo)
{
    int row = blockIdx.x;                       // b*NS + s
    const float* s = enc_emb + (size_t)src_ids[row] * NE;
    for (int k = threadIdx.x; k < NE; k += blockDim.x) {
        float v = s[k];
        bf16 hv = __float2bfloat16(v);
        hi[(size_t)row * NE + k] = hv;
        lo[(size_t)row * NE + k] = __float2bfloat16(v - __bfloat162float(hv));
    }
}

__global__ void embed_dec_hl(const int* __restrict__ tgt_ids,
                             const float* __restrict__ dec_emb,
                             bf16* __restrict__ hi, bf16* __restrict__ lo)
{
    int row = blockIdx.x;                       // t*NB + b  (padded to 1536)
    bool valid = row < NTm1 * NB;
    int t = row / NB, b = row % NB;
    const float* s = valid ? (dec_emb + (size_t)tgt_ids[b * NT + t] * NE) : nullptr;
    for (int k = threadIdx.x; k < NE; k += blockDim.x) {
        float v = valid ? s[k] : 0.f;
        bf16 hv = __float2bfloat16(v);
        hi[(size_t)row * NE + k] = hv;
        lo[(size_t)row * NE + k] = __float2bfloat16(v - __bfloat162float(hv));
    }
}

// ---------------- weight panel packing ----------------------------------------
__global__ void pack_w(const float* __restrict__ W, float* __restrict__ Wp,
                       int ldw, int koff)
{
    int col = blockIdx.y;            // 0..3071 = jb*24 + c
    int jb = col / 24, c = col % 24;
    int g = c >> 3, jj = c & 7;
    int row = g * NH + jb * 8 + jj;
    for (int k = blockIdx.x * 256 + threadIdx.x; k < NH; k += gridDim.x * 256)
        Wp[((size_t)jb * NH + k) * 24 + c] = W[(size_t)row * ldw + koff + k];
}

// ---------------- fused GRU layer step ----------------------------------------
template<bool MERGE>
__global__ __launch_bounds__(256) void gru_fused(
    const float* __restrict__ A1, int lda1, const float* __restrict__ W1p, long wjb1,
    const float* __restrict__ A2, int lda2, const float* __restrict__ W2p, long wjb2,
    int NK,
    const float* __restrict__ gi_pre, long gi_stride,
    const float* __restrict__ bih, const float* __restrict__ bhh,
    const float* __restrict__ h_in, float* __restrict__ h_out,
    float* __restrict__ extra, long extra_stride)
{
    __shared__ float sA1[32][34];
    __shared__ float sW1[32][26];
    __shared__ float sA2[32][34];
    __shared__ float sW2[32][26];
    __shared__ float sG1[32][24];
    __shared__ float sG2[32][24];

    const int jb = blockIdx.x;       // 0..127
    const int tid = threadIdx.x;
    const int grp = tid >> 7;
    const int t2 = tid & 127;
    const int cg = t2 & 7;
    const int mg = t2 >> 3;          // 0..15
    const int m0 = mg * 2;
    const int c0 = cg * 3;

    float acc[2][3] = {{0.f,0.f,0.f},{0.f,0.f,0.f}};

    const float (*sA)[34] = grp ? sA2 : sA1;
    const float (*sW)[26] = grp ? sW2 : sW1;

    const float* Wblk1 = W1p + (size_t)jb * wjb1;
    const float* Wblk2 = W2p + (size_t)jb * wjb2;

    for (int it = 0; it < NK; it++) {
        const int k0 = it * 32;
#pragma unroll
        for (int e = tid; e < 1024; e += 256) {
            int m = e >> 5, kk = e & 31;
            sA1[kk][m] = A1[(size_t)m * lda1 + k0 + kk];
            sA2[kk][m] = A2[(size_t)m * lda2 + k0 + kk];
        }
#pragma unroll
        for (int e = tid; e < 768; e += 256) {
            int kk = e / 24, c = e % 24;
            sW1[kk][c] = Wblk1[(size_t)(k0 + kk) * 24 + c];
            sW2[kk][c] = Wblk2[(size_t)(k0 + kk) * 24 + c];
        }
        __syncthreads();
#pragma unroll
        for (int kk = 0; kk < 32; kk++) {
            float a0 = sA[kk][m0], a1 = sA[kk][m0 + 1];
            float w0 = sW[kk][c0], w1 = sW[kk][c0 + 1], w2 = sW[kk][c0 + 2];
            acc[0][0] += a0 * w0; acc[0][1] += a0 * w1; acc[0][2] += a0 * w2;
            acc[1][0] += a1 * w0; acc[1][1] += a1 * w1; acc[1][2] += a1 * w2;
        }
        __syncthreads();
    }

    float (*sO)[24] = grp ? sG2 : sG1;
    sO[m0  ][c0] = acc[0][0]; sO[m0  ][c0+1] = acc[0][1]; sO[m0  ][c0+2] = acc[0][2];
    sO[m0+1][c0] = acc[1][0]; sO[m0+1][c0+1] = acc[1][1]; sO[m0+1][c0+2] = acc[1][2];
    __syncthreads();

    const int m = tid >> 3;
    const int jj = tid & 7;
    const int j = jb * 8 + jj;

    float g1r = sG1[m][jj], g1z = sG1[m][8+jj], g1n = sG1[m][16+jj];
    float ghr = sG2[m][jj], ghz = sG2[m][8+jj], ghn = sG2[m][16+jj];
    float gir, giz, gin;
    if (MERGE) { ghr += g1r; ghz += g1z; ghn += g1n; gir = giz = gin = 0.f; }
    else       { gir = g1r;  giz = g1z;  gin = g1n; }
    if (gi_pre) {
        const float* gp = gi_pre + (size_t)m * gi_stride;
        gir += gp[j]; giz += gp[NH + j]; gin += gp[2*NH + j];
    }
    if (bih) { gir += bih[j]; giz += bih[NH + j]; gin += bih[2*NH + j]; }
    ghr += bhh[j]; ghz += bhh[NH + j]; ghn += bhh[2*NH + j];

    float r = 1.f / (1.f + expf(-(gir + ghr)));
    float z = 1.f / (1.f + expf(-(giz + ghz)));
    float n = tanhf(gin + r * ghn);
    float hv = h_in[(size_t)m * NH + j];
    float hn = (1.f - z) * n + z * hv;
    h_out[(size_t)m * NH + j] = hn;
    if (extra) extra[(size_t)m * extra_stride + j] = hn;
}

// ---------------- attention (per-step) ----------------------------------------
__global__ void attn_kernel(const float* __restrict__ proj,
                            const float* __restrict__ enc_out,
                            const float* __restrict__ d1,
                            const int*   __restrict__ src_ids,
                            float* __restrict__ ctx_out,
                            float* __restrict__ ctx2, long ctx2_stride)
{
    int b   = blockIdx.x;
    int tid = threadIdx.x;            // 256 threads
    int warp = tid >> 5, lane = tid & 31;

    __shared__ float s_d1[NH];
    __shared__ float s_sc[NS];
    __shared__ float s_attn[NS];

    for (int i = tid; i < NH; i += 256) s_d1[i] = d1[(size_t)b * NH + i];
    __syncthreads();

    for (int s = warp; s < NS; s += 8) {
        const float* pr = proj + (size_t)(s * NB + b) * NH;
        float acc = 0.f;
        for (int k = lane; k < NH; k += 32) acc += pr[k] * s_d1[k];
#pragma unroll
        for (int off = 16; off; off >>= 1) acc += __shfl_xor_sync(0xffffffffu, acc, off);
        if (lane == 0)
            s_sc[s] = (src_ids[b * NS + s] != 0) ? acc : -1e9f;
    }
    __syncthreads();

    if (warp == 0) {
        float v0 = s_sc[lane], v1 = s_sc[lane + 32];
        float m = fmaxf(v0, v1);
#pragma unroll
        for (int off = 16; off; off >>= 1) m = fmaxf(m, __shfl_xor_sync(0xffffffffu, m, off));
        float e0 = expf(v0 - m), e1 = expf(v1 - m);
        float sum = e0 + e1;
#pragma unroll
        for (int off = 16; off; off >>= 1) sum += __shfl_xor_sync(0xffffffffu, sum, off);
        float inv = 1.f / sum;
        s_attn[lane]      = e0 * inv;
        s_attn[lane + 32] = e1 * inv;
    }
    __syncthreads();

    for (int jj = tid; jj < NH; jj += 256) {
        float acc = 0.f;
#pragma unroll 8
        for (int s = 0; s < NS; s++)
            acc += s_attn[s] * enc_out[(size_t)(s * NB + b) * NH + jj];
        ctx_out[(size_t)b * NH + jj] = acc;
        ctx2[(size_t)b * ctx2_stride + jj] = acc;
    }
}

// ---------------- small helpers -----------------------------------------------
__global__ void zero_kernel(float* a, int n)
{
    int i = blockIdx.x * blockDim.x + threadIdx.x;
    if (i < n) a[i] = 0.f;
}

__global__ void bias_kernel(float* __restrict__ out, const float* __restrict__ bias)
{
    int idx = blockIdx.x * blockDim.x + threadIdx.x;   // over 1504*8000 float4
    if (idx >= NTm1 * NB * (NV/4)) return;
    int n4 = idx % (NV/4);
    float4 v = ((float4*)out)[idx];
    float4 bv = ((const float4*)bias)[n4];
    v.x += bv.x; v.y += bv.y; v.z += bv.z; v.w += bv.w;
    ((float4*)out)[idx] = v;
}

// ---------------- host orchestration -----------------------------------------
extern "C" void kernel_launch(void* const* d_in, const int* in_sizes, int n_in,
                              void* d_out, int out_size)
{
    const int*   src_ids  = (const int*)  d_in[0];
    const int*   tgt_ids  = (const int*)  d_in[2];
    const float* enc_emb  = (const float*)d_in[3];
    const float* dec_emb  = (const float*)d_in[4];
    const float* enc_wih0 = (const float*)d_in[5];
    const float* enc_whh0 = (const float*)d_in[6];
    const float* enc_bih0 = (const float*)d_in[7];
    const float* enc_bhh0 = (const float*)d_in[8];
    const float* enc_wih1 = (const float*)d_in[9];
    const float* enc_whh1 = (const float*)d_in[10];
    const float* enc_bih1 = (const float*)d_in[11];
    const float* enc_bhh1 = (const float*)d_in[12];
    const float* dec_wih0 = (const float*)d_in[13];
    const float* dec_whh0 = (const float*)d_in[14];
    const float* dec_bih0 = (const float*)d_in[15];
    const float* dec_bhh0 = (const float*)d_in[16];
    const float* dec_wih1 = (const float*)d_in[17];
    const float* dec_whh1 = (const float*)d_in[18];
    const float* dec_bih1 = (const float*)d_in[19];
    const float* dec_bhh1 = (const float*)d_in[20];
    const float* attn_w   = (const float*)d_in[21];
    const float* out_w    = (const float*)d_in[22];
    const float* out_b    = (const float*)d_in[23];
    float* out = (float*)d_out;

    float *p_gi0,*p_gi1,*p_giemb,*p_h0seq,*p_encout,*p_proj,*p_ctx;
    float *p_d0a,*p_d0b,*p_d1a,*p_d1b,*p_zero,*p_d1ctx;
    float *pw_ewhh0,*pw_ewhh1,*pw_dwih0c,*pw_dwhh0,*pw_dwih1,*pw_dwhh1;
    bf16 *p_Ahi,*p_Alo,*p_Whi,*p_Wlo;
    bf16 *p_cembh,*p_cembl,*p_cdembh,*p_cdembl,*p_ch0h,*p_ch0l,*p_ceoh,*p_ceol;
    bf16 *p_wih0h,*p_wih0l,*p_dwih0eh,*p_dwih0el,*p_wih1h,*p_wih1l,*p_attnwh,*p_attnwl;
    cudaGetSymbolAddress((void**)&p_gi0,    g_gi0);
    cudaGetSymbolAddress((void**)&p_gi1,    g_gi1);
    cudaGetSymbolAddress((void**)&p_giemb,  g_giemb);
    cudaGetSymbolAddress((void**)&p_h0seq,  g_h0seq);
    cudaGetSymbolAddress((void**)&p_encout, g_encout);
    cudaGetSymbolAddress((void**)&p_proj,   g_proj);
    cudaGetSymbolAddress((void**)&p_ctx,    g_ctx);
    cudaGetSymbolAddress((void**)&p_d0a,    g_d0a);
    cudaGetSymbolAddress((void**)&p_d0b,    g_d0b);
    cudaGetSymbolAddress((void**)&p_d1a,    g_d1a);
    cudaGetSymbolAddress((void**)&p_d1b,    g_d1b);
    cudaGetSymbolAddress((void**)&p_zero,   g_zero);
    cudaGetSymbolAddress((void**)&p_d1ctx,  g_d1ctx);
    cudaGetSymbolAddress((void**)&pw_ewhh0, g_p_ewhh0);
    cudaGetSymbolAddress((void**)&pw_ewhh1, g_p_ewhh1);
    cudaGetSymbolAddress((void**)&pw_dwih0c,g_p_dwih0c);
    cudaGetSymbolAddress((void**)&pw_dwhh0, g_p_dwhh0);
    cudaGetSymbolAddress((void**)&pw_dwih1, g_p_dwih1);
    cudaGetSymbolAddress((void**)&pw_dwhh1, g_p_dwhh1);
    cudaGetSymbolAddress((void**)&p_Ahi,    g_Ahi);
    cudaGetSymbolAddress((void**)&p_Alo,    g_Alo);
    cudaGetSymbolAddress((void**)&p_Whi,    g_Whi);
    cudaGetSymbolAddress((void**)&p_Wlo,    g_Wlo);
    cudaGetSymbolAddress((void**)&p_cembh,  g_cembh);
    cudaGetSymbolAddress((void**)&p_cembl,  g_cembl);
    cudaGetSymbolAddress((void**)&p_cdembh, g_cdembh);
    cudaGetSymbolAddress((void**)&p_cdembl, g_cdembl);
    cudaGetSymbolAddress((void**)&p_ch0h,   g_ch0h);
    cudaGetSymbolAddress((void**)&p_ch0l,   g_ch0l);
    cudaGetSymbolAddress((void**)&p_ceoh,   g_ceoh);
    cudaGetSymbolAddress((void**)&p_ceol,   g_ceol);
    cudaGetSymbolAddress((void**)&p_wih0h,  g_wih0h);
    cudaGetSymbolAddress((void**)&p_wih0l,  g_wih0l);
    cudaGetSymbolAddress((void**)&p_dwih0eh,g_dwih0eh);
    cudaGetSymbolAddress((void**)&p_dwih0el,g_dwih0el);
    cudaGetSymbolAddress((void**)&p_wih1h,  g_wih1h);
    cudaGetSymbolAddress((void**)&p_wih1l,  g_wih1l);
    cudaGetSymbolAddress((void**)&p_attnwh, g_attnwh);
    cudaGetSymbolAddress((void**)&p_attnwl, g_attnwl);

    const long WJB = (long)NH * 24;
    const int SMEM_HL = 8 * SBUF * (int)sizeof(bf16);   // 81920 B
    cudaFuncSetAttribute(gemm_hl, cudaFuncAttributeMaxDynamicSharedMemorySize, SMEM_HL);

    // ---- prep: packing + conversions ----------------------------------------
    zero_kernel<<<(NB*NH + 255)/256, 256>>>(p_zero, NB*NH);
    pack_w<<<dim3(4, NH3), 256>>>(enc_whh0, pw_ewhh0, NH, 0);
    pack_w<<<dim3(4, NH3), 256>>>(enc_whh1, pw_ewhh1, NH, 0);
    pack_w<<<dim3(4, NH3), 256>>>(dec_wih0, pw_dwih0c, NE + NH, NE);
    pack_w<<<dim3(4, NH3), 256>>>(dec_whh0, pw_dwhh0, NH, 0);
    pack_w<<<dim3(4, NH3), 256>>>(dec_wih1, pw_dwih1, NH, 0);
    pack_w<<<dim3(4, NH3), 256>>>(dec_whh1, pw_dwhh1, NH, 0);

    conv_hl<<<NV, 256>>>(out_w, 2*NH, p_Whi, p_Wlo, NV, 2*NH);
    conv_hl<<<NH3, 256>>>(enc_wih0, NE, p_wih0h, p_wih0l, NH3, NE);
    conv_hl<<<NH3, 256>>>(dec_wih0, NE + NH, p_dwih0eh, p_dwih0el, NH3, NE);
    conv_hl<<<NH3, 256>>>(enc_wih1, NH, p_wih1h, p_wih1l, NH3, NH);
    conv_hl<<<NH,  256>>>(attn_w,   NH, p_attnwh, p_attnwl, NH, NH);

    embed_enc_hl<<<NB*NS, 128>>>(src_ids, enc_emb, p_cembh, p_cembl);
    embed_dec_hl<<<1536,  128>>>(tgt_ids, dec_emb, p_cdembh, p_cdembl);

    // batched input-gate GEMMs (tensor cores)
    gemm_hl<<<dim3(16, 24), 256, SMEM_HL>>>(p_cembh, p_cembl, p_wih0h, p_wih0l,
                                            p_gi0, NH3, NE, NB*NS);
    gemm_hl<<<dim3(12, 24), 256, SMEM_HL>>>(p_cdembh, p_cdembl, p_dwih0eh, p_dwih0el,
                                            p_giemb, NH3, NE, NTm1*NB);

    // ---- encoder layer 0 -----------------------------------------------------
    for (int s = 0; s < NS; s++) {
        const float* hp = s ? (p_h0seq + (size_t)(s-1)*NB*NH) : p_zero;
        gru_fused<true><<<128, 256>>>(
            hp + 512, NH, pw_ewhh0 + 512*24, WJB,
            hp,       NH, pw_ewhh0,          WJB,
            16,
            p_gi0 + (size_t)s * NH3, (long)NS * NH3,
            enc_bih0, enc_bhh0,
            hp, p_h0seq + (size_t)s*NB*NH, nullptr, 0);
    }

    // encoder layer-1 input gates (batched)
    conv_hl<<<NS*NB, 256>>>(p_h0seq, NH, p_ch0h, p_ch0l, NS*NB, NH);
    gemm_hl<<<dim3(16, 24), 256, SMEM_HL>>>(p_ch0h, p_ch0l, p_wih1h, p_wih1l,
                                            p_gi1, NH3, NH, NS*NB);

    // ---- encoder layer 1 -----------------------------------------------------
    for (int s = 0; s < NS; s++) {
        const float* hp = s ? (p_encout + (size_t)(s-1)*NB*NH) : p_zero;
        gru_fused<true><<<128, 256>>>(
            hp + 512, NH, pw_ewhh1 + 512*24, WJB,
            hp,       NH, pw_ewhh1,          WJB,
            16,
            p_gi1 + (size_t)s * NB * NH3, (long)NH3,
            enc_bih1, enc_bhh1,
            hp, p_encout + (size_t)s*NB*NH, nullptr, 0);
    }

    // attention projection (tensor cores)
    conv_hl<<<NS*NB, 256>>>(p_encout, NH, p_ceoh, p_ceol, NS*NB, NH);
    gemm_hl<<<dim3(16, 8), 256, SMEM_HL>>>(p_ceoh, p_ceol, p_attnwh, p_attnwl,
                                           p_proj, NH, NH, NS*NB);

    // ---- decoder -------------------------------------------------------------
    const float* d0_prev = p_h0seq  + (size_t)(NS-1)*NB*NH;
    const float* d1_prev = p_encout + (size_t)(NS-1)*NB*NH;
    for (int t = 0; t < NTm1; t++) {
        attn_kernel<<<NB, 256>>>(
            p_proj, p_encout, d1_prev, src_ids,
            p_ctx, p_d1ctx + (size_t)t * 2 * NH + NH, (long)NTm1 * 2 * NH);

        float* d0_new = (t & 1) ? p_d0b : p_d0a;
        gru_fused<false><<<128, 256>>>(
            p_ctx, NH, pw_dwih0c, WJB,
            d0_prev, NH, pw_dwhh0, WJB,
            32,
            p_giemb + (size_t)t * NB * NH3, (long)NH3,
            dec_bih0, dec_bhh0,
            d0_prev, d0_new, nullptr, 0);

        float* d1_new = (t & 1) ? p_d1b : p_d1a;
        gru_fused<false><<<128, 256>>>(
            d0_new, NH, pw_dwih1, WJB,
            d1_prev, NH, pw_dwhh1, WJB,
            32,
            nullptr, 0,
            dec_bih1, dec_bhh1,
            d1_prev, d1_new,
            p_d1ctx + (size_t)t * 2 * NH, (long)NTm1 * 2 * NH);

        d0_prev = d0_new;
        d1_prev = d1_new;
    }

    // ---- output projection (tensor cores) ------------------------------------
    conv_hl<<<1536, 256>>>(p_d1ctx, 2*NH, p_Ahi, p_Alo, NTm1*NB, 2*NH);
    gemm_hl<<<dim3(12, NV/128), 256, SMEM_HL>>>(p_Ahi, p_Alo, p_Whi, p_Wlo,
                                                out, NV, 2*NH, NTm1*NB);
    bias_kernel<<<(NTm1*NB*(NV/4) + 255)/256, 256>>>(out, out_b);

    (void)in_sizes; (void)n_in; (void)out_size;
}

// round 5
// speedup vs baseline: 8.4670x; 1.0235x over previous
#include <cuda_runtime.h>
#include <cuda_bf16.h>
#include <mma.h>
#include <math.h>
#include <stdint.h>

using namespace nvcuda;
typedef __nv_bfloat16 bf16;

// Problem constants
constexpr int NB  = 32;     // batch
constexpr int NS  = 64;     // src len
constexpr int NT  = 48;     // tgt len
constexpr int NTm1= 47;     // decode steps
constexpr int NV  = 32000;  // vocab
constexpr int NE  = 512;    // embed
constexpr int NH  = 1024;   // hidden
constexpr int NH3 = 3072;   // 3*H
constexpr int PGRID = 128;  // persistent grid (must be <= 148 for co-residency)

// ---------------- scratch (device globals; no allocation allowed) -------------
__device__ float g_gi0   [NB*NS*NH3];       // enc l0 input gates (rows b*NS+s)
__device__ float g_gi1   [NS*NB*NH3];       // enc l1 input gates (rows s*NB+b)
__device__ float g_giemb [NTm1*NB*NH3];     // dec l0 emb-part gates (rows t*NB+b)
__device__ float g_h0seq [NS*NB*NH];        // enc l0 hidden per step (s-major)
__device__ float g_encout[NS*NB*NH];        // enc l1 hidden per step (s-major)
__device__ float g_proj  [NS*NB*NH];        // attn-projected enc out (s-major)
__device__ float g_ctx   [NB*NH];
__device__ float g_score [NB*NS];
__device__ float g_d0a[NB*NH], g_d0b[NB*NH];
__device__ float g_d1a[NB*NH], g_d1b[NB*NH];
__device__ float g_zero  [NB*NH];
__device__ float g_d1ctx [NTm1*NB*2*NH];    // rows (b*NTm1+t): [d1 | ctx]

// packed recurrent weights: [jb(128)][k(1024)][c(24)]  c = gate*8 + jj
__device__ float g_p_ewhh0[128*NH*24];
__device__ float g_p_ewhh1[128*NH*24];
__device__ float g_p_dwih0c[128*NH*24];     // dec_wih0[:, 512:1536]
__device__ float g_p_dwhh0[128*NH*24];
__device__ float g_p_dwih1[128*NH*24];
__device__ float g_p_dwhh1[128*NH*24];

// bf16 hi/lo splits
__device__ bf16 g_Ahi[1536*2048],  g_Alo[1536*2048];       // d1ctx
__device__ bf16 g_Whi[(size_t)NV*2048], g_Wlo[(size_t)NV*2048];   // out_w
__device__ bf16 g_cembh[2048*512],  g_cembl[2048*512];     // enc embeddings
__device__ bf16 g_cdembh[1536*512], g_cdembl[1536*512];    // dec embeddings (pad)
__device__ bf16 g_ch0h[2048*1024],  g_ch0l[2048*1024];     // h0seq
__device__ bf16 g_ceoh[2048*1024],  g_ceol[2048*1024];     // encout
__device__ bf16 g_wih0h[3072*512],  g_wih0l[3072*512];     // enc_wih0
__device__ bf16 g_dwih0eh[3072*512],g_dwih0el[3072*512];   // dec_wih0[:, :512]
__device__ bf16 g_wih1h[3072*1024], g_wih1l[3072*1024];    // enc_wih1
__device__ bf16 g_attnwh[1024*1024],g_attnwl[1024*1024];   // attn_w

// ---------------- software grid barrier ---------------------------------------
__device__ unsigned g_bar_cnt = 0;
__device__ unsigned g_bar_gen = 0;

__device__ __forceinline__ void grid_sync()
{
    __threadfence();
    __syncthreads();
    if (threadIdx.x == 0) {
        unsigned g = *(volatile unsigned*)&g_bar_gen;
        unsigned prev = atomicAdd(&g_bar_cnt, 1u);
        if (prev == (unsigned)gridDim.x - 1u) {
            g_bar_cnt = 0;
            __threadfence();
            atomicAdd(&g_bar_gen, 1u);
        } else {
            while (*(volatile unsigned*)&g_bar_gen == g) __nanosleep(32);
        }
    }
    __syncthreads();
}

// ============ pipelined hi/lo bf16 tensor-core GEMM ===========================
constexpr int GLD  = 40;            // smem leading dim (elements)
constexpr int SBUF = 128 * GLD;     // one 128x32 buffer (padded)

__device__ __forceinline__ void cp16(bf16* s, const bf16* g)
{
    unsigned saddr = (unsigned)__cvta_generic_to_shared(s);
    asm volatile("cp.async.cg.shared.global [%0], [%1], 16;\n" :: "r"(saddr), "l"(g));
}

__device__ __forceinline__ void gemm_hl_load(
    int tid, int st, int k0, int bm, int bn, int K,
    const bf16* __restrict__ Ahi, const bf16* __restrict__ Alo,
    const bf16* __restrict__ Bhi, const bf16* __restrict__ Blo,
    bf16* sm)
{
#pragma unroll
    for (int i = 0; i < 8; i++) {
        int e = tid + i * 256;
        int buf = e >> 9;                 // 0..3 (constant per unrolled i)
        int r   = (e >> 2) & 127;
        int q   = e & 3;
        const bf16* gsrc; int grow;
        if      (buf == 0) { gsrc = Ahi; grow = bm + r; }
        else if (buf == 1) { gsrc = Alo; grow = bm + r; }
        else if (buf == 2) { gsrc = Bhi; grow = bn + r; }
        else               { gsrc = Blo; grow = bn + r; }
        bf16* s = sm + (size_t)buf * 2 * SBUF + (size_t)st * SBUF + r * GLD + q * 8;
        cp16(s, gsrc + (size_t)grow * K + k0 + q * 8);
    }
}

__global__ __launch_bounds__(256) void gemm_hl(
    const bf16* __restrict__ Ahi, const bf16* __restrict__ Alo,
    const bf16* __restrict__ Bhi, const bf16* __restrict__ Blo,
    float* __restrict__ C, int N, int K, int Mstore)
{
    extern __shared__ bf16 sm[];
    const int bm = blockIdx.x * 128;
    const int bn = blockIdx.y * 128;
    const int tid = threadIdx.x;
    const int warp = tid >> 5;
    const int wm = warp >> 2, wn = warp & 3;   // 2 x 4 warps; warp tile 64 x 32

    wmma::fragment<wmma::accumulator,16,16,16,float> c[4][2];
#pragma unroll
    for (int i = 0; i < 4; i++)
#pragma unroll
        for (int j = 0; j < 2; j++) wmma::fill_fragment(c[i][j], 0.f);

    const int NTk = K >> 5;

    gemm_hl_load(tid, 0, 0, bm, bn, K, Ahi, Alo, Bhi, Blo, sm);
    asm volatile("cp.async.commit_group;\n");

    for (int it = 0; it < NTk; it++) {
        if (it + 1 < NTk) {
            gemm_hl_load(tid, (it + 1) & 1, (it + 1) << 5, bm, bn, K, Ahi, Alo, Bhi, Blo, sm);
            asm volatile("cp.async.commit_group;\n");
            asm volatile("cp.async.wait_group 1;\n");
        } else {
            asm volatile("cp.async.wait_group 0;\n");
        }
        __syncthreads();

        const int cur = it & 1;
        const bf16* pAh = sm + 0 * 2 * SBUF + cur * SBUF;
        const bf16* pAl = sm + 1 * 2 * SBUF + cur * SBUF;
        const bf16* pBh = sm + 2 * 2 * SBUF + cur * SBUF;
        const bf16* pBl = sm + 3 * 2 * SBUF + cur * SBUF;

#pragma unroll
        for (int ks = 0; ks < 2; ks++) {
            wmma::fragment<wmma::matrix_a,16,16,16,bf16,wmma::row_major> ah[4], al[4];
            wmma::fragment<wmma::matrix_b,16,16,16,bf16,wmma::col_major> bh[2], bl[2];
#pragma unroll
            for (int i = 0; i < 4; i++) {
                wmma::load_matrix_sync(ah[i], pAh + (wm*64 + i*16)*GLD + ks*16, GLD);
                wmma::load_matrix_sync(al[i], pAl + (wm*64 + i*16)*GLD + ks*16, GLD);
            }
#pragma unroll
            for (int j = 0; j < 2; j++) {
                wmma::load_matrix_sync(bh[j], pBh + (wn*32 + j*16)*GLD + ks*16, GLD);
                wmma::load_matrix_sync(bl[j], pBl + (wn*32 + j*16)*GLD + ks*16, GLD);
            }
#pragma unroll
            for (int i = 0; i < 4; i++)
#pragma unroll
                for (int j = 0; j < 2; j++) {
                    wmma::mma_sync(c[i][j], ah[i], bh[j], c[i][j]);
                    wmma::mma_sync(c[i][j], ah[i], bl[j], c[i][j]);
                    wmma::mma_sync(c[i][j], al[i], bh[j], c[i][j]);
                }
        }
        __syncthreads();
    }

#pragma unroll
    for (int i = 0; i < 4; i++) {
        int gm = bm + wm*64 + i*16;
        if (gm >= Mstore) continue;
#pragma unroll
        for (int j = 0; j < 2; j++)
            wmma::store_matrix_sync(&C[(size_t)gm * N + bn + wn*32 + j*16],
                                    c[i][j], N, wmma::mem_row_major);
    }
}

// ---------------- fp32 -> bf16 hi/lo conversion (one block per row) ----------
__global__ void conv_hl(const float* __restrict__ src, int lda,
                        bf16* __restrict__ hi, bf16* __restrict__ lo,
                        int Mreal, int K)
{
    int m = blockIdx.x;
    const float* s = src + (size_t)m * lda;
    bf16* h = hi + (size_t)m * K;
    bf16* l = lo + (size_t)m * K;
    bool valid = m < Mreal;
    for (int k = threadIdx.x; k < K; k += blockDim.x) {
        float v = valid ? s[k] : 0.f;
        bf16 hv = __float2bfloat16(v);
        h[k] = hv;
        l[k] = __float2bfloat16(v - __bfloat162float(hv));
    }
}

// embedding gather fused with hi/lo conversion
__global__ void embed_enc_hl(const int* __restrict__ src_ids,
                             const float* __restrict__ enc_emb,
                             bf16* __restrict__ hi, bf16* __restrict__ lo)
{
    int row = blockIdx.x;                       // b*NS + s
    const float* s = enc_emb + (size_t)src_ids[row] * NE;
    for (int k = threadIdx.x; k < NE; k += blockDim.x) {
        float v = s[k];
        bf16 hv = __float2bfloat16(v);
        hi[(size_t)row * NE + k] = hv;
        lo[(size_t)row * NE + k] = __float2bfloat16(v - __bfloat162float(hv));
    }
}

__global__ void embed_dec_hl(const int* __restrict__ tgt_ids,
                             const float* __restrict__ dec_emb,
                             bf16* __restrict__ hi, bf16* __restrict__ lo)
{
    int row = blockIdx.x;                       // t*NB + b  (padded to 1536)
    bool valid = row < NTm1 * NB;
    int t = row / NB, b = row % NB;
    const float* s = valid ? (dec_emb + (size_t)tgt_ids[b * NT + t] * NE) : nullptr;
    for (int k = threadIdx.x; k < NE; k += blockDim.x) {
        float v = valid ? s[k] : 0.f;
        bf16 hv = __float2bfloat16(v);
        hi[(size_t)row * NE + k] = hv;
        lo[(size_t)row * NE + k] = __float2bfloat16(v - __bfloat162float(hv));
    }
}

// ---------------- weight panel packing ----------------------------------------
__global__ void pack_w(const float* __restrict__ W, float* __restrict__ Wp,
                       int ldw, int koff)
{
    int col = blockIdx.y;            // 0..3071 = jb*24 + c
    int jb = col / 24, c = col % 24;
    int g = c >> 3, jj = c & 7;
    int row = g * NH + jb * 8 + jj;
    for (int k = blockIdx.x * 256 + threadIdx.x; k < NH; k += gridDim.x * 256)
        Wp[((size_t)jb * NH + k) * 24 + c] = W[(size_t)row * ldw + koff + k];
}

// ---------------- GRU step body (software-pipelined dual-job GEMM) -----------
// Two 128-thread jobs each compute a 32m x 24c panel GEMM; then gate epilogue.
// MERGE=true: both jobs are k-split halves of the gh GEMM; gi comes from gi_pre.
template<bool MERGE>
__device__ __forceinline__ void gru_body(
    const float* __restrict__ A1, int lda1, const float* __restrict__ W1,
    const float* __restrict__ A2, int lda2, const float* __restrict__ W2,
    int NK,
    const float* __restrict__ gp_base, long gi_mstride,
    const float* __restrict__ bih, const float* __restrict__ bhh,
    const float* __restrict__ h_in, float* __restrict__ h_out,
    float* __restrict__ extra, long extra_stride,
    int jb,
    float (*sA1)[34], float (*sW1)[26],
    float (*sA2)[34], float (*sW2)[26],
    float (*sG1)[24], float (*sG2)[24])
{
    const int tid = threadIdx.x;
    const int grp = tid >> 7;
    const int t2  = tid & 127;
    const int cg  = t2 & 7;
    const int mg  = t2 >> 3;
    const int m0  = mg * 2;
    const int c0  = cg * 3;

    int ma[4], ka[4], kw[3], cw[3];
#pragma unroll
    for (int i = 0; i < 4; i++) { int e = tid + i*256; ma[i] = e >> 5; ka[i] = e & 31; }
#pragma unroll
    for (int i = 0; i < 3; i++) { int f = tid + i*256; kw[i] = f / 24; cw[i] = f % 24; }

    float rA1[4], rA2[4], rW1[3], rW2[3];
#pragma unroll
    for (int i = 0; i < 4; i++) {
        rA1[i] = A1[(size_t)ma[i]*lda1 + ka[i]];
        rA2[i] = A2[(size_t)ma[i]*lda2 + ka[i]];
    }
#pragma unroll
    for (int i = 0; i < 3; i++) {
        rW1[i] = W1[(size_t)kw[i]*24 + cw[i]];
        rW2[i] = W2[(size_t)kw[i]*24 + cw[i]];
    }

    float acc[2][3] = {{0.f,0.f,0.f},{0.f,0.f,0.f}};
    const float (*sA)[34] = grp ? sA2 : sA1;
    const float (*sW)[26] = grp ? sW2 : sW1;

    for (int it = 0; it < NK; it++) {
        __syncthreads();    // previous tile's compute done; smem free
#pragma unroll
        for (int i = 0; i < 4; i++) { sA1[ka[i]][ma[i]] = rA1[i]; sA2[ka[i]][ma[i]] = rA2[i]; }
#pragma unroll
        for (int i = 0; i < 3; i++) { sW1[kw[i]][cw[i]] = rW1[i]; sW2[kw[i]][cw[i]] = rW2[i]; }
        __syncthreads();
        if (it + 1 < NK) {                       // prefetch next tile (hidden by compute)
            int k0 = (it + 1) << 5;
#pragma unroll
            for (int i = 0; i < 4; i++) {
                rA1[i] = A1[(size_t)ma[i]*lda1 + k0 + ka[i]];
                rA2[i] = A2[(size_t)ma[i]*lda2 + k0 + ka[i]];
            }
#pragma unroll
            for (int i = 0; i < 3; i++) {
                rW1[i] = W1[(size_t)(k0 + kw[i])*24 + cw[i]];
                rW2[i] = W2[(size_t)(k0 + kw[i])*24 + cw[i]];
            }
        }
#pragma unroll
        for (int kk = 0; kk < 32; kk++) {
            float a0 = sA[kk][m0], a1 = sA[kk][m0 + 1];
            float w0 = sW[kk][c0], w1 = sW[kk][c0 + 1], w2 = sW[kk][c0 + 2];
            acc[0][0] += a0 * w0; acc[0][1] += a0 * w1; acc[0][2] += a0 * w2;
            acc[1][0] += a1 * w0; acc[1][1] += a1 * w1; acc[1][2] += a1 * w2;
        }
    }

    float (*sO)[24] = grp ? sG2 : sG1;
    sO[m0  ][c0] = acc[0][0]; sO[m0  ][c0+1] = acc[0][1]; sO[m0  ][c0+2] = acc[0][2];
    sO[m0+1][c0] = acc[1][0]; sO[m0+1][c0+1] = acc[1][1]; sO[m0+1][c0+2] = acc[1][2];
    __syncthreads();

    const int m = tid >> 3;
    const int jj = tid & 7;
    const int j = jb * 8 + jj;

    float g1r = sG1[m][jj], g1z = sG1[m][8+jj], g1n = sG1[m][16+jj];
    float ghr = sG2[m][jj], ghz = sG2[m][8+jj], ghn = sG2[m][16+jj];
    float gir, giz, gin;
    if (MERGE) { ghr += g1r; ghz += g1z; ghn += g1n; gir = giz = gin = 0.f; }
    else       { gir = g1r;  giz = g1z;  gin = g1n; }
    if (gp_base) {
        const float* gp = gp_base + (size_t)m * gi_mstride;
        gir += gp[j]; giz += gp[NH + j]; gin += gp[2*NH + j];
    }
    if (bih) { gir += bih[j]; giz += bih[NH + j]; gin += bih[2*NH + j]; }
    ghr += bhh[j]; ghz += bhh[NH + j]; ghn += bhh[2*NH + j];

    float r = 1.f / (1.f + expf(-(gir + ghr)));
    float z = 1.f / (1.f + expf(-(giz + ghz)));
    float n = tanhf(gin + r * ghn);
    float hv = h_in[(size_t)m * NH + j];
    float hn = (1.f - z) * n + z * hv;
    h_out[(size_t)m * NH + j] = hn;
    if (extra) extra[(size_t)m * extra_stride + j] = hn;
}

// ---------------- persistent encoder layer ------------------------------------
__global__ __launch_bounds__(256) void enc_persist(
    const float* __restrict__ zero, float* __restrict__ hseq,
    const float* __restrict__ Wp,
    const float* __restrict__ gi_pre, long gi_sstride, long gi_mstride,
    const float* __restrict__ bih, const float* __restrict__ bhh)
{
    __shared__ float sA1[32][34], sW1[32][26], sA2[32][34], sW2[32][26];
    __shared__ float sG1[32][24], sG2[32][24];
    const int jb = blockIdx.x;
    const float* Wlo_ = Wp + (size_t)jb * (NH * 24);
    const float* Whi_ = Wlo_ + 512 * 24;

    for (int s = 0; s < NS; s++) {
        const float* hp = s ? hseq + (size_t)(s-1)*NB*NH : zero;
        gru_body<true>(hp + 512, NH, Whi_,
                       hp,       NH, Wlo_,
                       16,
                       gi_pre + (size_t)s * gi_sstride, gi_mstride,
                       bih, bhh, hp, hseq + (size_t)s*NB*NH,
                       nullptr, 0, jb,
                       sA1, sW1, sA2, sW2, sG1, sG2);
        grid_sync();
    }
}

// ---------------- persistent decoder ------------------------------------------
__global__ __launch_bounds__(256) void dec_persist(
    const float* __restrict__ proj, const float* __restrict__ encout,
    const int* __restrict__ src_ids,
    const float* __restrict__ giemb,
    const float* __restrict__ Wih0c, const float* __restrict__ Whh0,
    const float* __restrict__ Wih1,  const float* __restrict__ Whh1,
    const float* __restrict__ bih0, const float* __restrict__ bhh0,
    const float* __restrict__ bih1, const float* __restrict__ bhh1,
    const float* __restrict__ d0_init, const float* __restrict__ d1_init,
    float* __restrict__ d0a, float* __restrict__ d0b,
    float* __restrict__ d1a, float* __restrict__ d1b,
    float* __restrict__ ctx, float* __restrict__ score,
    float* __restrict__ d1ctx)
{
    __shared__ float sA1[32][34], sW1[32][26], sA2[32][34], sW2[32][26];
    __shared__ float sG1[32][24], sG2[32][24];
    __shared__ float s_attn[NS];

    const int tid = threadIdx.x;
    const int warp = tid >> 5, lane = tid & 31;
    const int jb = blockIdx.x;
    const long WJB = (long)NH * 24;
    const float* pWih0c = Wih0c + (size_t)jb * WJB;
    const float* pWhh0  = Whh0  + (size_t)jb * WJB;
    const float* pWih1  = Wih1  + (size_t)jb * WJB;
    const float* pWhh1  = Whh1  + (size_t)jb * WJB;

    const float* d0_prev = d0_init;
    const float* d1_prev = d1_init;

    for (int t = 0; t < NTm1; t++) {
        // ---- phase A: attention scores (2048 (b,s) pairs over 1024 warps) ----
        int wg = blockIdx.x * 8 + warp;
#pragma unroll
        for (int rep = 0; rep < 2; rep++) {
            int p = wg + rep * 1024;
            int b = p >> 6, s = p & 63;
            const float* pr = proj + (size_t)(s * NB + b) * NH;
            const float* dd = d1_prev + (size_t)b * NH;
            float a = 0.f;
            for (int k = lane; k < NH; k += 32) a += pr[k] * dd[k];
#pragma unroll
            for (int off = 16; off; off >>= 1) a += __shfl_xor_sync(0xffffffffu, a, off);
            if (lane == 0)
                score[p] = (src_ids[b * NS + s] != 0) ? a : -1e9f;
        }
        grid_sync();

        // ---- phase B: softmax + context (block -> (b, 256-j slice)) ----------
        {
            int b  = blockIdx.x >> 2;
            int j0 = (blockIdx.x & 3) * 256;
            if (warp == 0) {
                float v0 = score[b * 64 + lane], v1 = score[b * 64 + 32 + lane];
                float m = fmaxf(v0, v1);
#pragma unroll
                for (int off = 16; off; off >>= 1) m = fmaxf(m, __shfl_xor_sync(0xffffffffu, m, off));
                float e0 = expf(v0 - m), e1 = expf(v1 - m);
                float sum = e0 + e1;
#pragma unroll
                for (int off = 16; off; off >>= 1) sum += __shfl_xor_sync(0xffffffffu, sum, off);
                float inv = 1.f / sum;
                s_attn[lane]      = e0 * inv;
                s_attn[lane + 32] = e1 * inv;
            }
            __syncthreads();
            int j = j0 + tid;
            float a = 0.f;
#pragma unroll 8
            for (int s = 0; s < NS; s++)
                a += s_attn[s] * encout[(size_t)(s * NB + b) * NH + j];
            ctx[(size_t)b * NH + j] = a;
            d1ctx[(size_t)b * NTm1 * 2 * NH + (size_t)t * 2 * NH + NH + j] = a;
        }
        grid_sync();

        // ---- phase C: decoder GRU layer 0 ------------------------------------
        float* d0_new = (t & 1) ? d0b : d0a;
        gru_body<false>(ctx, NH, pWih0c,
                        d0_prev, NH, pWhh0,
                        32,
                        giemb + (size_t)t * NB * NH3, (long)NH3,
                        bih0, bhh0, d0_prev, d0_new, nullptr, 0, jb,
                        sA1, sW1, sA2, sW2, sG1, sG2);
        grid_sync();

        // ---- phase D: decoder GRU layer 1 ------------------------------------
        float* d1_new = (t & 1) ? d1b : d1a;
        gru_body<false>(d0_new, NH, pWih1,
                        d1_prev, NH, pWhh1,
                        32,
                        nullptr, 0,
                        bih1, bhh1, d1_prev, d1_new,
                        d1ctx + (size_t)t * 2 * NH, (long)NTm1 * 2 * NH, jb,
                        sA1, sW1, sA2, sW2, sG1, sG2);
        grid_sync();

        d0_prev = d0_new;
        d1_prev = d1_new;
    }
}

// ---------------- small helpers -----------------------------------------------
__global__ void zero_kernel(float* a, int n)
{
    int i = blockIdx.x * blockDim.x + threadIdx.x;
    if (i < n) a[i] = 0.f;
}

__global__ void bias_kernel(float* __restrict__ out, const float* __restrict__ bias)
{
    int idx = blockIdx.x * blockDim.x + threadIdx.x;   // over 1504*8000 float4
    if (idx >= NTm1 * NB * (NV/4)) return;
    int n4 = idx % (NV/4);
    float4 v = ((float4*)out)[idx];
    float4 bv = ((const float4*)bias)[n4];
    v.x += bv.x; v.y += bv.y; v.z += bv.z; v.w += bv.w;
    ((float4*)out)[idx] = v;
}

// ---------------- host orchestration -----------------------------------------
extern "C" void kernel_launch(void* const* d_in, const int* in_sizes, int n_in,
                              void* d_out, int out_size)
{
    const int*   src_ids  = (const int*)  d_in[0];
    const int*   tgt_ids  = (const int*)  d_in[2];
    const float* enc_emb  = (const float*)d_in[3];
    const float* dec_emb  = (const float*)d_in[4];
    const float* enc_wih0 = (const float*)d_in[5];
    const float* enc_whh0 = (const float*)d_in[6];
    const float* enc_bih0 = (const float*)d_in[7];
    const float* enc_bhh0 = (const float*)d_in[8];
    const float* enc_wih1 = (const float*)d_in[9];
    const float* enc_whh1 = (const float*)d_in[10];
    const float* enc_bih1 = (const float*)d_in[11];
    const float* enc_bhh1 = (const float*)d_in[12];
    const float* dec_wih0 = (const float*)d_in[13];
    const float* dec_whh0 = (const float*)d_in[14];
    const float* dec_bih0 = (const float*)d_in[15];
    const float* dec_bhh0 = (const float*)d_in[16];
    const float* dec_wih1 = (const float*)d_in[17];
    const float* dec_whh1 = (const float*)d_in[18];
    const float* dec_bih1 = (const float*)d_in[19];
    const float* dec_bhh1 = (const float*)d_in[20];
    const float* attn_w   = (const float*)d_in[21];
    const float* out_w    = (const float*)d_in[22];
    const float* out_b    = (const float*)d_in[23];
    float* out = (float*)d_out;

    float *p_gi0,*p_gi1,*p_giemb,*p_h0seq,*p_encout,*p_proj,*p_ctx,*p_score;
    float *p_d0a,*p_d0b,*p_d1a,*p_d1b,*p_zero,*p_d1ctx;
    float *pw_ewhh0,*pw_ewhh1,*pw_dwih0c,*pw_dwhh0,*pw_dwih1,*pw_dwhh1;
    bf16 *p_Ahi,*p_Alo,*p_Whi,*p_Wlo;
    bf16 *p_cembh,*p_cembl,*p_cdembh,*p_cdembl,*p_ch0h,*p_ch0l,*p_ceoh,*p_ceol;
    bf16 *p_wih0h,*p_wih0l,*p_dwih0eh,*p_dwih0el,*p_wih1h,*p_wih1l,*p_attnwh,*p_attnwl;
    cudaGetSymbolAddress((void**)&p_gi0,    g_gi0);
    cudaGetSymbolAddress((void**)&p_gi1,    g_gi1);
    cudaGetSymbolAddress((void**)&p_giemb,  g_giemb);
    cudaGetSymbolAddress((void**)&p_h0seq,  g_h0seq);
    cudaGetSymbolAddress((void**)&p_encout, g_encout);
    cudaGetSymbolAddress((void**)&p_proj,   g_proj);
    cudaGetSymbolAddress((void**)&p_ctx,    g_ctx);
    cudaGetSymbolAddress((void**)&p_score,  g_score);
    cudaGetSymbolAddress((void**)&p_d0a,    g_d0a);
    cudaGetSymbolAddress((void**)&p_d0b,    g_d0b);
    cudaGetSymbolAddress((void**)&p_d1a,    g_d1a);
    cudaGetSymbolAddress((void**)&p_d1b,    g_d1b);
    cudaGetSymbolAddress((void**)&p_zero,   g_zero);
    cudaGetSymbolAddress((void**)&p_d1ctx,  g_d1ctx);
    cudaGetSymbolAddress((void**)&pw_ewhh0, g_p_ewhh0);
    cudaGetSymbolAddress((void**)&pw_ewhh1, g_p_ewhh1);
    cudaGetSymbolAddress((void**)&pw_dwih0c,g_p_dwih0c);
    cudaGetSymbolAddress((void**)&pw_dwhh0, g_p_dwhh0);
    cudaGetSymbolAddress((void**)&pw_dwih1, g_p_dwih1);
    cudaGetSymbolAddress((void**)&pw_dwhh1, g_p_dwhh1);
    cudaGetSymbolAddress((void**)&p_Ahi,    g_Ahi);
    cudaGetSymbolAddress((void**)&p_Alo,    g_Alo);
    cudaGetSymbolAddress((void**)&p_Whi,    g_Whi);
    cudaGetSymbolAddress((void**)&p_Wlo,    g_Wlo);
    cudaGetSymbolAddress((void**)&p_cembh,  g_cembh);
    cudaGetSymbolAddress((void**)&p_cembl,  g_cembl);
    cudaGetSymbolAddress((void**)&p_cdembh, g_cdembh);
    cudaGetSymbolAddress((void**)&p_cdembl, g_cdembl);
    cudaGetSymbolAddress((void**)&p_ch0h,   g_ch0h);
    cudaGetSymbolAddress((void**)&p_ch0l,   g_ch0l);
    cudaGetSymbolAddress((void**)&p_ceoh,   g_ceoh);
    cudaGetSymbolAddress((void**)&p_ceol,   g_ceol);
    cudaGetSymbolAddress((void**)&p_wih0h,  g_wih0h);
    cudaGetSymbolAddress((void**)&p_wih0l,  g_wih0l);
    cudaGetSymbolAddress((void**)&p_dwih0eh,g_dwih0eh);
    cudaGetSymbolAddress((void**)&p_dwih0el,g_dwih0el);
    cudaGetSymbolAddress((void**)&p_wih1h,  g_wih1h);
    cudaGetSymbolAddress((void**)&p_wih1l,  g_wih1l);
    cudaGetSymbolAddress((void**)&p_attnwh, g_attnwh);
    cudaGetSymbolAddress((void**)&p_attnwl, g_attnwl);

    const int SMEM_HL = 8 * SBUF * (int)sizeof(bf16);   // 81920 B
    cudaFuncSetAttribute(gemm_hl, cudaFuncAttributeMaxDynamicSharedMemorySize, SMEM_HL);

    // ---- prep: packing + conversions ----------------------------------------
    zero_kernel<<<(NB*NH + 255)/256, 256>>>(p_zero, NB*NH);
    pack_w<<<dim3(4, NH3), 256>>>(enc_whh0, pw_ewhh0, NH, 0);
    pack_w<<<dim3(4, NH3), 256>>>(enc_whh1, pw_ewhh1, NH, 0);
    pack_w<<<dim3(4, NH3), 256>>>(dec_wih0, pw_dwih0c, NE + NH, NE);
    pack_w<<<dim3(4, NH3), 256>>>(dec_whh0, pw_dwhh0, NH, 0);
    pack_w<<<dim3(4, NH3), 256>>>(dec_wih1, pw_dwih1, NH, 0);
    pack_w<<<dim3(4, NH3), 256>>>(dec_whh1, pw_dwhh1, NH, 0);

    conv_hl<<<NV, 256>>>(out_w, 2*NH, p_Whi, p_Wlo, NV, 2*NH);
    conv_hl<<<NH3, 256>>>(enc_wih0, NE, p_wih0h, p_wih0l, NH3, NE);
    conv_hl<<<NH3, 256>>>(dec_wih0, NE + NH, p_dwih0eh, p_dwih0el, NH3, NE);
    conv_hl<<<NH3, 256>>>(enc_wih1, NH, p_wih1h, p_wih1l, NH3, NH);
    conv_hl<<<NH,  256>>>(attn_w,   NH, p_attnwh, p_attnwl, NH, NH);

    embed_enc_hl<<<NB*NS, 128>>>(src_ids, enc_emb, p_cembh, p_cembl);
    embed_dec_hl<<<1536,  128>>>(tgt_ids, dec_emb, p_cdembh, p_cdembl);

    // batched input-gate GEMMs (tensor cores)
    gemm_hl<<<dim3(16, 24), 256, SMEM_HL>>>(p_cembh, p_cembl, p_wih0h, p_wih0l,
                                            p_gi0, NH3, NE, NB*NS);
    gemm_hl<<<dim3(12, 24), 256, SMEM_HL>>>(p_cdembh, p_cdembl, p_dwih0eh, p_dwih0el,
                                            p_giemb, NH3, NE, NTm1*NB);

    // ---- encoder layer 0 (persistent, 64 steps, grid-synced) -----------------
    enc_persist<<<PGRID, 256>>>(p_zero, p_h0seq, pw_ewhh0,
                                p_gi0, (long)NH3, (long)NS*NH3,
                                enc_bih0, enc_bhh0);

    // encoder layer-1 input gates (batched, tensor cores)
    conv_hl<<<NS*NB, 256>>>(p_h0seq, NH, p_ch0h, p_ch0l, NS*NB, NH);
    gemm_hl<<<dim3(16, 24), 256, SMEM_HL>>>(p_ch0h, p_ch0l, p_wih1h, p_wih1l,
                                            p_gi1, NH3, NH, NS*NB);

    // ---- encoder layer 1 (persistent) ----------------------------------------
    enc_persist<<<PGRID, 256>>>(p_zero, p_encout, pw_ewhh1,
                                p_gi1, (long)NB*NH3, (long)NH3,
                                enc_bih1, enc_bhh1);

    // attention projection (tensor cores)
    conv_hl<<<NS*NB, 256>>>(p_encout, NH, p_ceoh, p_ceol, NS*NB, NH);
    gemm_hl<<<dim3(16, 8), 256, SMEM_HL>>>(p_ceoh, p_ceol, p_attnwh, p_attnwl,
                                           p_proj, NH, NH, NS*NB);

    // ---- decoder (single persistent kernel: attention + 2 GRU layers) --------
    dec_persist<<<PGRID, 256>>>(p_proj, p_encout, src_ids, p_giemb,
                                pw_dwih0c, pw_dwhh0, pw_dwih1, pw_dwhh1,
                                dec_bih0, dec_bhh0, dec_bih1, dec_bhh1,
                                p_h0seq  + (size_t)(NS-1)*NB*NH,
                                p_encout + (size_t)(NS-1)*NB*NH,
                                p_d0a, p_d0b, p_d1a, p_d1b,
                                p_ctx, p_score, p_d1ctx);

    // ---- output projection (tensor cores) ------------------------------------
    conv_hl<<<1536, 256>>>(p_d1ctx, 2*NH, p_Ahi, p_Alo, NTm1*NB, 2*NH);
    gemm_hl<<<dim3(12, NV/128), 256, SMEM_HL>>>(p_Ahi, p_Alo, p_Whi, p_Wlo,
                                                out, NV, 2*NH, NTm1*NB);
    bias_kernel<<<(NTm1*NB*(NV/4) + 255)/256, 256>>>(out, out_b);

    (void)in_sizes; (void)n_in; (void)out_size;
}